// round 8
// baseline (speedup 1.0000x reference)
#include <cuda_runtime.h>
#include <math.h>

#define NT 2048
#define NH 2048
#define NI 1408
#define NE 8
#define TK 2
#define NP (NT*TK)

#define BM   128
#define BN   64
#define BK   32
#define ASTR 36    // [m][k], %32==4 -> A-frag reads hit banks 4*grp+tig (bijective)
#define BSTR 72    // [k][n], %32==8 -> B-frag reads hit banks 8*tig+grp (bijective)

// ---------------- scratch ----------------
__device__ int   g_cnt[NE];
__device__ int   g_off[NE + 1];
__device__ int   g_tok[NP];
__device__ float g_wt[NP];
__device__ float g_hid[(size_t)NT * NH];   // tf32-rounded hidden (16 MB)
__device__ float g_act[(size_t)NP * NI];   // tf32-rounded silu(g)*u (23 MB)

// ---------------- helpers ----------------
__device__ __forceinline__ unsigned rtf(float f) {
    return __float_as_uint(f) + 0x1000u;   // RN-to-tf32 when HMMA truncates
}
__device__ __forceinline__ uint4 rtf4(float4 v) {
    uint4 r;
    r.x = rtf(v.x); r.y = rtf(v.y); r.z = rtf(v.z); r.w = rtf(v.w);
    return r;
}
__device__ __forceinline__ void mma8(float* c, const unsigned* a, const unsigned* b) {
    asm volatile(
        "mma.sync.aligned.m16n8k8.row.col.f32.tf32.tf32.f32 "
        "{%0,%1,%2,%3},{%4,%5,%6,%7},{%8,%9},{%0,%1,%2,%3};"
        : "+f"(c[0]), "+f"(c[1]), "+f"(c[2]), "+f"(c[3])
        : "r"(a[0]), "r"(a[1]), "r"(a[2]), "r"(a[3]), "r"(b[0]), "r"(b[1]));
}
__device__ __forceinline__ unsigned smaddr(const void* p) {
    unsigned a;
    asm("{ .reg .u64 t; cvta.to.shared.u64 t, %1; cvt.u32.u64 %0, t; }" : "=r"(a) : "l"(p));
    return a;
}
__device__ __forceinline__ void cpa16(unsigned dst, const void* src) {
    asm volatile("cp.async.cg.shared.global [%0], [%1], 16;" :: "r"(dst), "l"(src) : "memory");
}
__device__ __forceinline__ void cpa_commit() {
    asm volatile("cp.async.commit_group;" ::: "memory");
}
__device__ __forceinline__ void cpa_wait0() {
    asm volatile("cp.async.wait_group 0;" ::: "memory");
}

// ---------------- fused routing ----------------
__global__ __launch_bounds__(1024) void k_route(
    const int* __restrict__ idx, const float* __restrict__ w)
{
    __shared__ int scnt[NE], soff[NE], sfill[NE];
    int tid = threadIdx.x;
    if (tid < NE) { scnt[tid] = 0; sfill[tid] = 0; }
    __syncthreads();
    int my_e[4];
#pragma unroll
    for (int j = 0; j < 4; j++) {
        int i = tid + j * 1024;
        my_e[j] = idx[i];
        atomicAdd(&scnt[my_e[j]], 1);
    }
    __syncthreads();
    if (tid == 0) {
        int s = 0;
        for (int e = 0; e < NE; e++) {
            soff[e] = s; g_off[e] = s; g_cnt[e] = scnt[e]; s += scnt[e];
        }
        g_off[NE] = s;
    }
    __syncthreads();
#pragma unroll
    for (int j = 0; j < 4; j++) {
        int i = tid + j * 1024;
        int e = my_e[j];
        int pos = soff[e] + atomicAdd(&sfill[e], 1);
        g_tok[pos] = i / TK;
        g_wt[pos]  = w[i];
    }
}

// pre-round hidden to tf32 bits, and zero out
__global__ void k_prep(const float* __restrict__ hidden, float* __restrict__ out) {
    int i = blockIdx.x * blockDim.x + threadIdx.x;
    uint4 v = rtf4(((const float4*)hidden)[i]);
    ((uint4*)g_hid)[i] = v;
    ((float4*)out)[i] = make_float4(0.f, 0.f, 0.f, 0.f);
}

#define A_WORDS (2 * BM * ASTR)
#define B_WORDS (2 * BK * BSTR)

// ---------------- GEMM1: act = silu(X Wg) * (X Wu) ----------------
// A (gathered pre-rounded hidden) via cp.async; B (weights) via LDG->rtf->STS.
__global__ __launch_bounds__(256) void k_gemm1(
    const float* __restrict__ gate_w,
    const float* __restrict__ up_w)
{
    extern __shared__ unsigned sm[];
    unsigned* sA  = sm;
    unsigned* sBg = sA + A_WORDS;
    unsigned* sBu = sBg + B_WORDS;
    int* toks = (int*)(sBu + B_WORDS);

    int e = blockIdx.z, cnt = g_cnt[e];
    int m0 = blockIdx.y * BM;
    if (m0 >= cnt) return;
    int base = g_off[e];
    int n0 = blockIdx.x * BN;
    int tid = threadIdx.x;

    if (tid < BM) {
        int m = m0 + tid;
        toks[tid] = (m < cnt) ? g_tok[base + m] : g_tok[base];
    }
    __syncthreads();

    const float* gp = gate_w + (size_t)e * NH * NI;
    const float* up = up_w   + (size_t)e * NH * NI;

    // A staging via cp.async: 2 threads per row, 16 floats each
    int a_m = tid >> 1, a_h = (tid & 1) << 4;
    const float* aSrc = g_hid + (size_t)toks[a_m] * NH + a_h;
    unsigned aDst = smaddr(&sA[a_m * ASTR + a_h]);

    // B staging via registers: 16 threads per k-row, float4, 2 k-passes
    int b_k = tid >> 4, b_n = (tid & 15) << 2;
    const float* gSrc = gp + (size_t)b_k * NI + n0 + b_n;
    const float* uSrc = up + (size_t)b_k * NI + n0 + b_n;

#define STAGE1A(buf, koff) do { \
    unsigned ao = (buf) * (BM * ASTR * 4u); \
    cpa16(aDst + ao,      aSrc + (koff)); \
    cpa16(aDst + ao + 16, aSrc + (koff) + 4); \
    cpa16(aDst + ao + 32, aSrc + (koff) + 8); \
    cpa16(aDst + ao + 48, aSrc + (koff) + 12); \
    cpa_commit(); \
} while (0)

    // prologue: buffer 0
    STAGE1A(0, 0);
    {
#pragma unroll
        for (int p = 0; p < 2; p++) {
            int k = b_k + p * 16;
            float4 vg = *(const float4*)(gSrc + (size_t)(p * 16) * NI);
            float4 vu = *(const float4*)(uSrc + (size_t)(p * 16) * NI);
            *(uint4*)&sBg[k * BSTR + b_n] = rtf4(vg);
            *(uint4*)&sBu[k * BSTR + b_n] = rtf4(vu);
        }
    }
    cpa_wait0();
    __syncthreads();

    int lane = tid & 31, wid = tid >> 5;
    int wm = (wid & 3) * 32, wn = (wid >> 2) * 32;
    int grp = lane >> 2, tig = lane & 3;

    float accg[2][4][4] = {}, accu[2][4][4] = {};
    float4 pg[2], pu[2];

    for (int k0 = 0; k0 < NH; k0 += BK) {
        int s = (k0 / BK) & 1;
        bool nxt = (k0 + BK) < NH;
        if (nxt) {
            int kn = k0 + BK;
            STAGE1A(s ^ 1, kn);
#pragma unroll
            for (int p = 0; p < 2; p++) {
                pg[p] = *(const float4*)(gSrc + (size_t)(kn + p * 16) * NI);
                pu[p] = *(const float4*)(uSrc + (size_t)(kn + p * 16) * NI);
            }
        }

        const unsigned* As = sA  + s * BM * ASTR;
        const unsigned* Bg = sBg + s * BK * BSTR;
        const unsigned* Bu = sBu + s * BK * BSTR;

#pragma unroll
        for (int kk = 0; kk < 4; kk++) {
            int k8 = kk * 8;
            unsigned a[2][4];
#pragma unroll
            for (int mi = 0; mi < 2; mi++) {
                int mb = wm + mi * 16 + grp;
                a[mi][0] = As[(mb    ) * ASTR + k8 + tig    ];
                a[mi][1] = As[(mb + 8) * ASTR + k8 + tig    ];
                a[mi][2] = As[(mb    ) * ASTR + k8 + tig + 4];
                a[mi][3] = As[(mb + 8) * ASTR + k8 + tig + 4];
            }
#pragma unroll
            for (int nj = 0; nj < 4; nj++) {
                int nb = wn + nj * 8 + grp;
                unsigned b[2];
                b[0] = Bg[(k8 + tig) * BSTR + nb];
                b[1] = Bg[(k8 + tig + 4) * BSTR + nb];
                mma8(accg[0][nj], a[0], b);
                mma8(accg[1][nj], a[1], b);
                b[0] = Bu[(k8 + tig) * BSTR + nb];
                b[1] = Bu[(k8 + tig + 4) * BSTR + nb];
                mma8(accu[0][nj], a[0], b);
                mma8(accu[1][nj], a[1], b);
            }
        }

        if (nxt) {
            int sn = s ^ 1;
            unsigned* Bgn = sBg + sn * BK * BSTR;
            unsigned* Bun = sBu + sn * BK * BSTR;
#pragma unroll
            for (int p = 0; p < 2; p++) {
                int k = b_k + p * 16;
                *(uint4*)&Bgn[k * BSTR + b_n] = rtf4(pg[p]);
                *(uint4*)&Bun[k * BSTR + b_n] = rtf4(pu[p]);
            }
            cpa_wait0();
        }
        __syncthreads();
    }

    // epilogue: silu(g)*u -> g_act (pre-rounded to tf32 bits for gemm2)
#pragma unroll
    for (int mi = 0; mi < 2; mi++) {
#pragma unroll
        for (int nj = 0; nj < 4; nj++) {
            int mrow = wm + mi * 16 + grp;
            int ncol = n0 + wn + nj * 8 + tig * 2;
#pragma unroll
            for (int h = 0; h < 2; h++) {
                int mr = m0 + mrow + h * 8;
                if (mr < cnt) {
                    float g0 = accg[mi][nj][2*h],     u0 = accu[mi][nj][2*h];
                    float g1 = accg[mi][nj][2*h + 1], u1 = accu[mi][nj][2*h + 1];
                    uint2 v;
                    v.x = rtf((g0 / (1.f + __expf(-g0))) * u0);
                    v.y = rtf((g1 / (1.f + __expf(-g1))) * u1);
                    *(uint2*)(g_act + (size_t)(base + mr) * NI + ncol) = v;
                }
            }
        }
    }
}

// ---------------- GEMM2: out[token] += wt * (act . Wd) ----------------
__global__ __launch_bounds__(256) void k_gemm2(
    const float* __restrict__ down_w,
    float* __restrict__ out)
{
    extern __shared__ unsigned sm[];
    unsigned* sA = sm;
    unsigned* sB = sA + A_WORDS;
    int*   toks = (int*)(sB + B_WORDS);
    float* wts  = (float*)(toks + BM);

    int e = blockIdx.z, cnt = g_cnt[e];
    int m0 = blockIdx.y * BM;
    if (m0 >= cnt) return;
    int base = g_off[e];
    int n0 = blockIdx.x * BN;
    int tid = threadIdx.x;

    if (tid < BM) {
        int m = m0 + tid;
        toks[tid] = (m < cnt) ? g_tok[base + m] : 0;
        wts[tid]  = (m < cnt) ? g_wt[base + m] : 0.f;
    }
    __syncthreads();

    const float* dp = down_w + (size_t)e * NI * NH;

    int a_m = tid >> 1, a_h = (tid & 1) << 4;
    int am = m0 + a_m;
    const float* aSrc = g_act + (size_t)(base + (am < cnt ? am : m0)) * NI + a_h;
    unsigned aDst = smaddr(&sA[a_m * ASTR + a_h]);

    int b_k = tid >> 4, b_n = (tid & 15) << 2;
    const float* bSrc = dp + (size_t)b_k * NH + n0 + b_n;

#define STAGE2A(buf, koff) do { \
    unsigned ao = (buf) * (BM * ASTR * 4u); \
    cpa16(aDst + ao,      aSrc + (koff)); \
    cpa16(aDst + ao + 16, aSrc + (koff) + 4); \
    cpa16(aDst + ao + 32, aSrc + (koff) + 8); \
    cpa16(aDst + ao + 48, aSrc + (koff) + 12); \
    cpa_commit(); \
} while (0)

    STAGE2A(0, 0);
    {
#pragma unroll
        for (int p = 0; p < 2; p++) {
            int k = b_k + p * 16;
            float4 v = *(const float4*)(bSrc + (size_t)(p * 16) * NH);
            *(uint4*)&sB[k * BSTR + b_n] = rtf4(v);
        }
    }
    cpa_wait0();
    __syncthreads();

    int lane = tid & 31, wid = tid >> 5;
    int wm = (wid & 3) * 32, wn = (wid >> 2) * 32;
    int grp = lane >> 2, tig = lane & 3;

    float acc[2][4][4] = {};
    float4 pb[2];

    for (int k0 = 0; k0 < NI; k0 += BK) {
        int s = (k0 / BK) & 1;
        bool nxt = (k0 + BK) < NI;
        if (nxt) {
            int kn = k0 + BK;
            STAGE2A(s ^ 1, kn);
#pragma unroll
            for (int p = 0; p < 2; p++)
                pb[p] = *(const float4*)(bSrc + (size_t)(kn + p * 16) * NH);
        }

        const unsigned* As = sA + s * BM * ASTR;
        const unsigned* Bs = sB + s * BK * BSTR;

#pragma unroll
        for (int kk = 0; kk < 4; kk++) {
            int k8 = kk * 8;
            unsigned a[2][4];
#pragma unroll
            for (int mi = 0; mi < 2; mi++) {
                int mb = wm + mi * 16 + grp;
                a[mi][0] = As[(mb    ) * ASTR + k8 + tig    ];
                a[mi][1] = As[(mb + 8) * ASTR + k8 + tig    ];
                a[mi][2] = As[(mb    ) * ASTR + k8 + tig + 4];
                a[mi][3] = As[(mb + 8) * ASTR + k8 + tig + 4];
            }
#pragma unroll
            for (int nj = 0; nj < 4; nj++) {
                int nb = wn + nj * 8 + grp;
                unsigned b[2];
                b[0] = Bs[(k8 + tig) * BSTR + nb];
                b[1] = Bs[(k8 + tig + 4) * BSTR + nb];
                mma8(acc[0][nj], a[0], b);
                mma8(acc[1][nj], a[1], b);
            }
        }

        if (nxt) {
            int sn = s ^ 1;
            unsigned* Bn = sB + sn * BK * BSTR;
#pragma unroll
            for (int p = 0; p < 2; p++) {
                int k = b_k + p * 16;
                *(uint4*)&Bn[k * BSTR + b_n] = rtf4(pb[p]);
            }
            cpa_wait0();
        }
        __syncthreads();
    }

#pragma unroll
    for (int mi = 0; mi < 2; mi++) {
#pragma unroll
        for (int nj = 0; nj < 4; nj++) {
            int mloc = wm + mi * 16 + grp;
            int ncol = n0 + wn + nj * 8 + tig * 2;
#pragma unroll
            for (int h = 0; h < 2; h++) {
                int ml = mloc + h * 8;
                int mr = m0 + ml;
                if (mr < cnt) {
                    int   t = toks[ml];
                    float w = wts[ml];
                    float* dst = out + (size_t)t * NH + ncol;
                    asm volatile("red.global.add.v2.f32 [%0], {%1,%2};"
                                 :: "l"(dst), "f"(w * acc[mi][nj][2*h]),
                                    "f"(w * acc[mi][nj][2*h + 1]) : "memory");
                }
            }
        }
    }
}

// ---------------- launch ----------------
extern "C" void kernel_launch(void* const* d_in, const int* in_sizes, int n_in,
                              void* d_out, int out_size)
{
    const float* hidden = (const float*)d_in[0];
    const int*   idx    = (const int*)  d_in[1];
    const float* topw   = (const float*)d_in[2];
    const float* gate_w = (const float*)d_in[3];
    const float* up_w   = (const float*)d_in[4];
    const float* down_w = (const float*)d_in[5];
    float* out = (float*)d_out;

    int smem1 = (A_WORDS + 2 * B_WORDS) * 4 + BM * 4;
    int smem2 = (A_WORDS + B_WORDS) * 4 + BM * 8;
    static int configured = 0;
    if (!configured) {
        cudaFuncSetAttribute(k_gemm1, cudaFuncAttributeMaxDynamicSharedMemorySize, smem1);
        cudaFuncSetAttribute(k_gemm2, cudaFuncAttributeMaxDynamicSharedMemorySize, smem2);
        configured = 1;
    }

    k_route<<<1, 1024>>>(idx, topw);
    k_prep<<<(NT * NH / 4) / 256, 256>>>(hidden, out);

    dim3 g1(NI / BN, NP / BM, NE);
    k_gemm1<<<g1, 256, smem1>>>(gate_w, up_w);

    dim3 g2(NH / BN, NP / BM, NE);
    k_gemm2<<<g2, 256, smem2>>>(down_w, out);
}

// round 9
// speedup vs baseline: 1.4245x; 1.4245x over previous
#include <cuda_runtime.h>
#include <math.h>

#define NT 2048
#define NH 2048
#define NI 1408
#define NE 8
#define TK 2
#define NP (NT*TK)

#define BM   128
#define BN   64
#define BK   32
#define ASTR 36    // [m][k], %32==4 -> A-frag reads hit banks 4*grp+tig (bijective)
#define BSTR 72    // [k][n], %32==8 -> B-frag reads hit banks 8*tig+grp (bijective)

// ---------------- scratch ----------------
__device__ int   g_cnt[NE];
__device__ int   g_off[NE + 1];
__device__ int   g_tok[NP];
__device__ float g_wt[NP];
__device__ float g_act[(size_t)NP * NI];

// ---------------- fused routing (one block) ----------------
__global__ __launch_bounds__(1024) void k_route(
    const int* __restrict__ idx, const float* __restrict__ w)
{
    __shared__ int scnt[NE], soff[NE], sfill[NE];
    int tid = threadIdx.x;
    if (tid < NE) { scnt[tid] = 0; sfill[tid] = 0; }
    __syncthreads();
    int my_e[4];
#pragma unroll
    for (int j = 0; j < 4; j++) {
        int i = tid + j * 1024;
        my_e[j] = idx[i];
        atomicAdd(&scnt[my_e[j]], 1);
    }
    __syncthreads();
    if (tid == 0) {
        int s = 0;
        for (int e = 0; e < NE; e++) {
            soff[e] = s; g_off[e] = s; g_cnt[e] = scnt[e]; s += scnt[e];
        }
        g_off[NE] = s;
    }
    __syncthreads();
#pragma unroll
    for (int j = 0; j < 4; j++) {
        int i = tid + j * 1024;
        int e = my_e[j];
        int pos = soff[e] + atomicAdd(&sfill[e], 1);
        g_tok[pos] = i / TK;
        g_wt[pos]  = w[i];
    }
}

__global__ void k_zero(float* __restrict__ out) {
    int i = blockIdx.x * blockDim.x + threadIdx.x;
    ((float4*)out)[i] = make_float4(0.f, 0.f, 0.f, 0.f);
}

// ---------------- tf32 helpers ----------------
// fp32 -> tf32 round-to-nearest via integer add (HMMA truncates low 13 bits).
__device__ __forceinline__ unsigned rtf(float f) {
    return __float_as_uint(f) + 0x1000u;
}
__device__ __forceinline__ uint4 rtf4(float4 v) {
    uint4 r;
    r.x = rtf(v.x); r.y = rtf(v.y); r.z = rtf(v.z); r.w = rtf(v.w);
    return r;
}
__device__ __forceinline__ void mma8(float* c, const unsigned* a, const unsigned* b) {
    asm volatile(
        "mma.sync.aligned.m16n8k8.row.col.f32.tf32.tf32.f32 "
        "{%0,%1,%2,%3},{%4,%5,%6,%7},{%8,%9},{%0,%1,%2,%3};"
        : "+f"(c[0]), "+f"(c[1]), "+f"(c[2]), "+f"(c[3])
        : "r"(a[0]), "r"(a[1]), "r"(a[2]), "r"(a[3]), "r"(b[0]), "r"(b[1]));
}

#define A_WORDS (2 * BM * ASTR)
#define B_WORDS (2 * BK * BSTR)

// ---------------- GEMM1: act = silu(X Wg) * (X Wu) ----------------
__global__ __launch_bounds__(256) void k_gemm1(
    const float* __restrict__ hidden,
    const float* __restrict__ gate_w,
    const float* __restrict__ up_w)
{
    extern __shared__ unsigned sm[];
    unsigned* sA  = sm;
    unsigned* sBg = sA + A_WORDS;
    unsigned* sBu = sBg + B_WORDS;
    int* toks = (int*)(sBu + B_WORDS);

    int e = blockIdx.z, cnt = g_cnt[e];
    int m0 = blockIdx.y * BM;
    if (m0 >= cnt) return;
    int base = g_off[e];
    int n0 = blockIdx.x * BN;
    int tid = threadIdx.x;

    if (tid < BM) {
        int m = m0 + tid;
        toks[tid] = (m < cnt) ? g_tok[base + m] : g_tok[base];
    }
    __syncthreads();

    const float* gp = gate_w + (size_t)e * NH * NI;
    const float* up = up_w   + (size_t)e * NH * NI;

    int a_m = tid >> 3, a_k = (tid & 7) << 2;
    int b_k = tid >> 4, b_n = (tid & 15) << 2;

    size_t arow[4];
#pragma unroll
    for (int p = 0; p < 4; p++) arow[p] = (size_t)toks[a_m + p * 32] * NH;

#pragma unroll
    for (int p = 0; p < 4; p++) {
        float4 v = *(const float4*)(hidden + arow[p] + a_k);
        *(uint4*)&sA[(size_t)(a_m + p * 32) * ASTR + a_k] = rtf4(v);
    }
#pragma unroll
    for (int p = 0; p < 2; p++) {
        int k = b_k + p * 16;
        float4 vg = *(const float4*)(gp + (size_t)k * NI + n0 + b_n);
        float4 vu = *(const float4*)(up + (size_t)k * NI + n0 + b_n);
        *(uint4*)&sBg[(size_t)k * BSTR + b_n] = rtf4(vg);
        *(uint4*)&sBu[(size_t)k * BSTR + b_n] = rtf4(vu);
    }
    __syncthreads();

    int lane = tid & 31, wid = tid >> 5;
    int wm = (wid & 3) * 32, wn = (wid >> 2) * 32;
    int grp = lane >> 2, tig = lane & 3;

    float accg[2][4][4] = {}, accu[2][4][4] = {};
    float4 pa[4], pg[2], pu[2];

    for (int k0 = 0; k0 < NH; k0 += BK) {
        int s = (k0 / BK) & 1;
        bool nxt = (k0 + BK) < NH;
        if (nxt) {
            int kn = k0 + BK;
#pragma unroll
            for (int p = 0; p < 4; p++)
                pa[p] = *(const float4*)(hidden + arow[p] + kn + a_k);
#pragma unroll
            for (int p = 0; p < 2; p++) {
                int k = b_k + p * 16;
                pg[p] = *(const float4*)(gp + (size_t)(kn + k) * NI + n0 + b_n);
                pu[p] = *(const float4*)(up + (size_t)(kn + k) * NI + n0 + b_n);
            }
        }

        const unsigned* As = sA  + (size_t)s * BM * ASTR;
        const unsigned* Bg = sBg + (size_t)s * BK * BSTR;
        const unsigned* Bu = sBu + (size_t)s * BK * BSTR;

#pragma unroll
        for (int kk = 0; kk < 4; kk++) {
            int k8 = kk * 8;
            unsigned a[2][4];
#pragma unroll
            for (int mi = 0; mi < 2; mi++) {
                int mb = wm + mi * 16 + grp;
                a[mi][0] = As[(mb    ) * ASTR + k8 + tig    ];
                a[mi][1] = As[(mb + 8) * ASTR + k8 + tig    ];
                a[mi][2] = As[(mb    ) * ASTR + k8 + tig + 4];
                a[mi][3] = As[(mb + 8) * ASTR + k8 + tig + 4];
            }
#pragma unroll
            for (int nj = 0; nj < 4; nj++) {
                int nb = wn + nj * 8 + grp;
                unsigned b[2];
                b[0] = Bg[(k8 + tig) * BSTR + nb];
                b[1] = Bg[(k8 + tig + 4) * BSTR + nb];
                mma8(accg[0][nj], a[0], b);
                mma8(accg[1][nj], a[1], b);
                b[0] = Bu[(k8 + tig) * BSTR + nb];
                b[1] = Bu[(k8 + tig + 4) * BSTR + nb];
                mma8(accu[0][nj], a[0], b);
                mma8(accu[1][nj], a[1], b);
            }
        }

        if (nxt) {
            int sn = s ^ 1;
            unsigned* An  = sA  + (size_t)sn * BM * ASTR;
            unsigned* Bgn = sBg + (size_t)sn * BK * BSTR;
            unsigned* Bun = sBu + (size_t)sn * BK * BSTR;
#pragma unroll
            for (int p = 0; p < 4; p++)
                *(uint4*)&An[(size_t)(a_m + p * 32) * ASTR + a_k] = rtf4(pa[p]);
#pragma unroll
            for (int p = 0; p < 2; p++) {
                int k = b_k + p * 16;
                *(uint4*)&Bgn[(size_t)k * BSTR + b_n] = rtf4(pg[p]);
                *(uint4*)&Bun[(size_t)k * BSTR + b_n] = rtf4(pu[p]);
            }
        }
        __syncthreads();
    }

#pragma unroll
    for (int mi = 0; mi < 2; mi++) {
#pragma unroll
        for (int nj = 0; nj < 4; nj++) {
            int mrow = wm + mi * 16 + grp;
            int ncol = n0 + wn + nj * 8 + tig * 2;
#pragma unroll
            for (int h = 0; h < 2; h++) {
                int mr = m0 + mrow + h * 8;
                if (mr < cnt) {
                    float g0 = accg[mi][nj][2*h],     u0 = accu[mi][nj][2*h];
                    float g1 = accg[mi][nj][2*h + 1], u1 = accu[mi][nj][2*h + 1];
                    float2 v;
                    v.x = (g0 / (1.f + __expf(-g0))) * u0;
                    v.y = (g1 / (1.f + __expf(-g1))) * u1;
                    *(float2*)(g_act + (size_t)(base + mr) * NI + ncol) = v;
                }
            }
        }
    }
}

// ---------------- GEMM2: out[token] += wt * (act . Wd) ----------------
__global__ __launch_bounds__(256) void k_gemm2(
    const float* __restrict__ down_w,
    float* __restrict__ out)
{
    extern __shared__ unsigned sm[];
    unsigned* sA = sm;
    unsigned* sB = sA + A_WORDS;
    int*   toks = (int*)(sB + B_WORDS);
    float* wts  = (float*)(toks + BM);

    int e = blockIdx.z, cnt = g_cnt[e];
    int m0 = blockIdx.y * BM;
    if (m0 >= cnt) return;
    int base = g_off[e];
    int n0 = blockIdx.x * BN;
    int tid = threadIdx.x;

    if (tid < BM) {
        int m = m0 + tid;
        toks[tid] = (m < cnt) ? g_tok[base + m] : 0;
        wts[tid]  = (m < cnt) ? g_wt[base + m] : 0.f;
    }
    __syncthreads();

    const float* dp = down_w + (size_t)e * NI * NH;

    int a_m = tid >> 3, a_k = (tid & 7) << 2;
    int b_k = tid >> 4, b_n = (tid & 15) << 2;

    size_t arow[4];
#pragma unroll
    for (int p = 0; p < 4; p++) {
        int m = m0 + a_m + p * 32;
        arow[p] = (size_t)(base + (m < cnt ? m : m0)) * NI;
    }

#pragma unroll
    for (int p = 0; p < 4; p++) {
        float4 v = *(const float4*)(g_act + arow[p] + a_k);
        *(uint4*)&sA[(size_t)(a_m + p * 32) * ASTR + a_k] = rtf4(v);
    }
#pragma unroll
    for (int p = 0; p < 2; p++) {
        int k = b_k + p * 16;
        float4 v = *(const float4*)(dp + (size_t)k * NH + n0 + b_n);
        *(uint4*)&sB[(size_t)k * BSTR + b_n] = rtf4(v);
    }
    __syncthreads();

    int lane = tid & 31, wid = tid >> 5;
    int wm = (wid & 3) * 32, wn = (wid >> 2) * 32;
    int grp = lane >> 2, tig = lane & 3;

    float acc[2][4][4] = {};
    float4 pa[4], pb[2];

    for (int k0 = 0; k0 < NI; k0 += BK) {
        int s = (k0 / BK) & 1;
        bool nxt = (k0 + BK) < NI;
        if (nxt) {
            int kn = k0 + BK;
#pragma unroll
            for (int p = 0; p < 4; p++)
                pa[p] = *(const float4*)(g_act + arow[p] + kn + a_k);
#pragma unroll
            for (int p = 0; p < 2; p++) {
                int k = b_k + p * 16;
                pb[p] = *(const float4*)(dp + (size_t)(kn + k) * NH + n0 + b_n);
            }
        }

        const unsigned* As = sA + (size_t)s * BM * ASTR;
        const unsigned* Bs = sB + (size_t)s * BK * BSTR;

#pragma unroll
        for (int kk = 0; kk < 4; kk++) {
            int k8 = kk * 8;
            unsigned a[2][4];
#pragma unroll
            for (int mi = 0; mi < 2; mi++) {
                int mb = wm + mi * 16 + grp;
                a[mi][0] = As[(mb    ) * ASTR + k8 + tig    ];
                a[mi][1] = As[(mb + 8) * ASTR + k8 + tig    ];
                a[mi][2] = As[(mb    ) * ASTR + k8 + tig + 4];
                a[mi][3] = As[(mb + 8) * ASTR + k8 + tig + 4];
            }
#pragma unroll
            for (int nj = 0; nj < 4; nj++) {
                int nb = wn + nj * 8 + grp;
                unsigned b[2];
                b[0] = Bs[(k8 + tig) * BSTR + nb];
                b[1] = Bs[(k8 + tig + 4) * BSTR + nb];
                mma8(acc[0][nj], a[0], b);
                mma8(acc[1][nj], a[1], b);
            }
        }

        if (nxt) {
            int sn = s ^ 1;
            unsigned* An = sA + (size_t)sn * BM * ASTR;
            unsigned* Bn = sB + (size_t)sn * BK * BSTR;
#pragma unroll
            for (int p = 0; p < 4; p++)
                *(uint4*)&An[(size_t)(a_m + p * 32) * ASTR + a_k] = rtf4(pa[p]);
#pragma unroll
            for (int p = 0; p < 2; p++) {
                int k = b_k + p * 16;
                *(uint4*)&Bn[(size_t)k * BSTR + b_n] = rtf4(pb[p]);
            }
        }
        __syncthreads();
    }

#pragma unroll
    for (int mi = 0; mi < 2; mi++) {
#pragma unroll
        for (int nj = 0; nj < 4; nj++) {
            int mloc = wm + mi * 16 + grp;
            int ncol = n0 + wn + nj * 8 + tig * 2;
#pragma unroll
            for (int h = 0; h < 2; h++) {
                int ml = mloc + h * 8;
                int mr = m0 + ml;
                if (mr < cnt) {
                    int   t = toks[ml];
                    float w = wts[ml];
                    float* dst = out + (size_t)t * NH + ncol;
                    asm volatile("red.global.add.v2.f32 [%0], {%1,%2};"
                                 :: "l"(dst), "f"(w * acc[mi][nj][2*h]),
                                    "f"(w * acc[mi][nj][2*h + 1]) : "memory");
                }
            }
        }
    }
}

// ---------------- launch ----------------
extern "C" void kernel_launch(void* const* d_in, const int* in_sizes, int n_in,
                              void* d_out, int out_size)
{
    const float* hidden = (const float*)d_in[0];
    const int*   idx    = (const int*)  d_in[1];
    const float* topw   = (const float*)d_in[2];
    const float* gate_w = (const float*)d_in[3];
    const float* up_w   = (const float*)d_in[4];
    const float* down_w = (const float*)d_in[5];
    float* out = (float*)d_out;

    int smem1 = (A_WORDS + 2 * B_WORDS) * 4 + BM * 4;
    int smem2 = (A_WORDS + B_WORDS) * 4 + BM * 8;
    static int configured = 0;
    if (!configured) {
        cudaFuncSetAttribute(k_gemm1, cudaFuncAttributeMaxDynamicSharedMemorySize, smem1);
        cudaFuncSetAttribute(k_gemm2, cudaFuncAttributeMaxDynamicSharedMemorySize, smem2);
        configured = 1;
    }

    k_route<<<1, 1024>>>(idx, topw);
    k_zero<<<(NT * NH / 4) / 256, 256>>>(out);

    dim3 g1(NI / BN, NP / BM, NE);
    k_gemm1<<<g1, 256, smem1>>>(hidden, gate_w, up_w);

    dim3 g2(NH / BN, NP / BM, NE);
    k_gemm2<<<g2, 256, smem2>>>(down_w, out);
}

// round 10
// speedup vs baseline: 1.4352x; 1.0075x over previous
#include <cuda_runtime.h>
#include <math.h>

#define NT 2048
#define NH 2048
#define NI 1408
#define NE 8
#define TK 2
#define NP (NT*TK)

#define BM   128
#define BN   64
#define BK   32
#define ASTR 36    // [m][k], %32==4 -> A-frag reads hit banks 4*grp+tig (bijective)
#define BSTR 72    // [k][n], %32==8 -> B-frag reads hit banks 8*tig+grp (bijective)

// ---------------- scratch ----------------
__device__ int   g_cnt[NE];
__device__ int   g_off[NE + 1];
__device__ int   g_tok[NP];
__device__ float g_wt[NP];
__device__ float g_act[(size_t)NP * NI];

// ---------------- fused routing (one block) ----------------
__global__ __launch_bounds__(1024) void k_route(
    const int* __restrict__ idx, const float* __restrict__ w)
{
    __shared__ int scnt[NE], soff[NE], sfill[NE];
    int tid = threadIdx.x;
    if (tid < NE) { scnt[tid] = 0; sfill[tid] = 0; }
    __syncthreads();
    int my_e[4];
#pragma unroll
    for (int j = 0; j < 4; j++) {
        int i = tid + j * 1024;
        my_e[j] = idx[i];
        atomicAdd(&scnt[my_e[j]], 1);
    }
    __syncthreads();
    if (tid == 0) {
        int s = 0;
        for (int e = 0; e < NE; e++) {
            soff[e] = s; g_off[e] = s; g_cnt[e] = scnt[e]; s += scnt[e];
        }
        g_off[NE] = s;
    }
    __syncthreads();
#pragma unroll
    for (int j = 0; j < 4; j++) {
        int i = tid + j * 1024;
        int e = my_e[j];
        int pos = soff[e] + atomicAdd(&sfill[e], 1);
        g_tok[pos] = i / TK;
        g_wt[pos]  = w[i];
    }
}

__global__ void k_zero(float* __restrict__ out) {
    int i = blockIdx.x * blockDim.x + threadIdx.x;
    ((float4*)out)[i] = make_float4(0.f, 0.f, 0.f, 0.f);
}

// ---------------- tf32 helpers ----------------
__device__ __forceinline__ unsigned rtf(float f) {
    return __float_as_uint(f) + 0x1000u;
}
__device__ __forceinline__ uint4 rtf4(float4 v) {
    uint4 r;
    r.x = rtf(v.x); r.y = rtf(v.y); r.z = rtf(v.z); r.w = rtf(v.w);
    return r;
}
__device__ __forceinline__ void mma8(float* c, const unsigned* a, const unsigned* b) {
    asm volatile(
        "mma.sync.aligned.m16n8k8.row.col.f32.tf32.tf32.f32 "
        "{%0,%1,%2,%3},{%4,%5,%6,%7},{%8,%9},{%0,%1,%2,%3};"
        : "+f"(c[0]), "+f"(c[1]), "+f"(c[2]), "+f"(c[3])
        : "r"(a[0]), "r"(a[1]), "r"(a[2]), "r"(a[3]), "r"(b[0]), "r"(b[1]));
}

#define A_WORDS (2 * BM * ASTR)
#define B_WORDS (2 * BK * BSTR)

// ---------------- GEMM1: act = silu(X Wg) * (X Wu) ----------------
__global__ __launch_bounds__(256, 2) void k_gemm1(
    const float* __restrict__ hidden,
    const float* __restrict__ gate_w,
    const float* __restrict__ up_w)
{
    extern __shared__ unsigned sm[];
    unsigned* sA  = sm;
    unsigned* sBg = sA + A_WORDS;
    unsigned* sBu = sBg + B_WORDS;
    int* toks = (int*)(sBu + B_WORDS);

    int e = blockIdx.z, cnt = g_cnt[e];
    int m0 = blockIdx.y * BM;
    if (m0 >= cnt) return;
    int base = g_off[e];
    int n0 = blockIdx.x * BN;
    int tid = threadIdx.x;

    if (tid < BM) {
        int m = m0 + tid;
        toks[tid] = (m < cnt) ? g_tok[base + m] : g_tok[base];
    }
    __syncthreads();

    const float* gp = gate_w + (size_t)e * NH * NI;
    const float* up = up_w   + (size_t)e * NH * NI;

    int a_m = tid >> 3, a_k = (tid & 7) << 2;
    int b_k = tid >> 4, b_n = (tid & 15) << 2;

    size_t arow[4];
#pragma unroll
    for (int p = 0; p < 4; p++) arow[p] = (size_t)toks[a_m + p * 32] * NH;

#pragma unroll
    for (int p = 0; p < 4; p++) {
        float4 v = *(const float4*)(hidden + arow[p] + a_k);
        *(uint4*)&sA[(size_t)(a_m + p * 32) * ASTR + a_k] = rtf4(v);
    }
#pragma unroll
    for (int p = 0; p < 2; p++) {
        int k = b_k + p * 16;
        float4 vg = *(const float4*)(gp + (size_t)k * NI + n0 + b_n);
        float4 vu = *(const float4*)(up + (size_t)k * NI + n0 + b_n);
        *(uint4*)&sBg[(size_t)k * BSTR + b_n] = rtf4(vg);
        *(uint4*)&sBu[(size_t)k * BSTR + b_n] = rtf4(vu);
    }
    __syncthreads();

    int lane = tid & 31, wid = tid >> 5;
    int wm = (wid & 3) * 32, wn = (wid >> 2) * 32;
    int grp = lane >> 2, tig = lane & 3;

    float accg[2][4][4] = {}, accu[2][4][4] = {};
    float4 pa[4], pg[2], pu[2];

    for (int k0 = 0; k0 < NH; k0 += BK) {
        int s = (k0 / BK) & 1;
        bool nxt = (k0 + BK) < NH;
        if (nxt) {
            int kn = k0 + BK;
#pragma unroll
            for (int p = 0; p < 4; p++)
                pa[p] = *(const float4*)(hidden + arow[p] + kn + a_k);
#pragma unroll
            for (int p = 0; p < 2; p++) {
                int k = b_k + p * 16;
                pg[p] = *(const float4*)(gp + (size_t)(kn + k) * NI + n0 + b_n);
                pu[p] = *(const float4*)(up + (size_t)(kn + k) * NI + n0 + b_n);
            }
        }

        const unsigned* As = sA  + (size_t)s * BM * ASTR;
        const unsigned* Bg = sBg + (size_t)s * BK * BSTR;
        const unsigned* Bu = sBu + (size_t)s * BK * BSTR;

#pragma unroll
        for (int kk = 0; kk < 4; kk++) {
            int k8 = kk * 8;
            unsigned a[2][4];
#pragma unroll
            for (int mi = 0; mi < 2; mi++) {
                int mb = wm + mi * 16 + grp;
                a[mi][0] = As[(mb    ) * ASTR + k8 + tig    ];
                a[mi][1] = As[(mb + 8) * ASTR + k8 + tig    ];
                a[mi][2] = As[(mb    ) * ASTR + k8 + tig + 4];
                a[mi][3] = As[(mb + 8) * ASTR + k8 + tig + 4];
            }
#pragma unroll
            for (int nj = 0; nj < 4; nj++) {
                int nb = wn + nj * 8 + grp;
                unsigned b[2];
                b[0] = Bg[(k8 + tig) * BSTR + nb];
                b[1] = Bg[(k8 + tig + 4) * BSTR + nb];
                mma8(accg[0][nj], a[0], b);
                mma8(accg[1][nj], a[1], b);
                b[0] = Bu[(k8 + tig) * BSTR + nb];
                b[1] = Bu[(k8 + tig + 4) * BSTR + nb];
                mma8(accu[0][nj], a[0], b);
                mma8(accu[1][nj], a[1], b);
            }
        }

        if (nxt) {
            int sn = s ^ 1;
            unsigned* An  = sA  + (size_t)sn * BM * ASTR;
            unsigned* Bgn = sBg + (size_t)sn * BK * BSTR;
            unsigned* Bun = sBu + (size_t)sn * BK * BSTR;
#pragma unroll
            for (int p = 0; p < 4; p++)
                *(uint4*)&An[(size_t)(a_m + p * 32) * ASTR + a_k] = rtf4(pa[p]);
#pragma unroll
            for (int p = 0; p < 2; p++) {
                int k = b_k + p * 16;
                *(uint4*)&Bgn[(size_t)k * BSTR + b_n] = rtf4(pg[p]);
                *(uint4*)&Bun[(size_t)k * BSTR + b_n] = rtf4(pu[p]);
            }
        }
        __syncthreads();
    }

#pragma unroll
    for (int mi = 0; mi < 2; mi++) {
#pragma unroll
        for (int nj = 0; nj < 4; nj++) {
            int mrow = wm + mi * 16 + grp;
            int ncol = n0 + wn + nj * 8 + tig * 2;
#pragma unroll
            for (int h = 0; h < 2; h++) {
                int mr = m0 + mrow + h * 8;
                if (mr < cnt) {
                    float g0 = accg[mi][nj][2*h],     u0 = accu[mi][nj][2*h];
                    float g1 = accg[mi][nj][2*h + 1], u1 = accu[mi][nj][2*h + 1];
                    float2 v;
                    v.x = (g0 / (1.f + __expf(-g0))) * u0;
                    v.y = (g1 / (1.f + __expf(-g1))) * u1;
                    *(float2*)(g_act + (size_t)(base + mr) * NI + ncol) = v;
                }
            }
        }
    }
}

// ---------------- GEMM2: out[token] += wt * (act . Wd) ----------------
__global__ __launch_bounds__(256, 3) void k_gemm2(
    const float* __restrict__ down_w,
    float* __restrict__ out)
{
    extern __shared__ unsigned sm[];
    unsigned* sA = sm;
    unsigned* sB = sA + A_WORDS;
    int*   toks = (int*)(sB + B_WORDS);
    float* wts  = (float*)(toks + BM);

    int e = blockIdx.z, cnt = g_cnt[e];
    int m0 = blockIdx.y * BM;
    if (m0 >= cnt) return;
    int base = g_off[e];
    int n0 = blockIdx.x * BN;
    int tid = threadIdx.x;

    if (tid < BM) {
        int m = m0 + tid;
        toks[tid] = (m < cnt) ? g_tok[base + m] : 0;
        wts[tid]  = (m < cnt) ? g_wt[base + m] : 0.f;
    }
    __syncthreads();

    const float* dp = down_w + (size_t)e * NI * NH;

    int a_m = tid >> 3, a_k = (tid & 7) << 2;
    int b_k = tid >> 4, b_n = (tid & 15) << 2;

    size_t arow[4];
#pragma unroll
    for (int p = 0; p < 4; p++) {
        int m = m0 + a_m + p * 32;
        arow[p] = (size_t)(base + (m < cnt ? m : m0)) * NI;
    }

#pragma unroll
    for (int p = 0; p < 4; p++) {
        float4 v = *(const float4*)(g_act + arow[p] + a_k);
        *(uint4*)&sA[(size_t)(a_m + p * 32) * ASTR + a_k] = rtf4(v);
    }
#pragma unroll
    for (int p = 0; p < 2; p++) {
        int k = b_k + p * 16;
        float4 v = *(const float4*)(dp + (size_t)k * NH + n0 + b_n);
        *(uint4*)&sB[(size_t)k * BSTR + b_n] = rtf4(v);
    }
    __syncthreads();

    int lane = tid & 31, wid = tid >> 5;
    int wm = (wid & 3) * 32, wn = (wid >> 2) * 32;
    int grp = lane >> 2, tig = lane & 3;

    float acc[2][4][4] = {};
    float4 pa[4], pb[2];

    for (int k0 = 0; k0 < NI; k0 += BK) {
        int s = (k0 / BK) & 1;
        bool nxt = (k0 + BK) < NI;
        if (nxt) {
            int kn = k0 + BK;
#pragma unroll
            for (int p = 0; p < 4; p++)
                pa[p] = *(const float4*)(g_act + arow[p] + kn + a_k);
#pragma unroll
            for (int p = 0; p < 2; p++) {
                int k = b_k + p * 16;
                pb[p] = *(const float4*)(dp + (size_t)(kn + k) * NH + n0 + b_n);
            }
        }

        const unsigned* As = sA + (size_t)s * BM * ASTR;
        const unsigned* Bs = sB + (size_t)s * BK * BSTR;

#pragma unroll
        for (int kk = 0; kk < 4; kk++) {
            int k8 = kk * 8;
            unsigned a[2][4];
#pragma unroll
            for (int mi = 0; mi < 2; mi++) {
                int mb = wm + mi * 16 + grp;
                a[mi][0] = As[(mb    ) * ASTR + k8 + tig    ];
                a[mi][1] = As[(mb + 8) * ASTR + k8 + tig    ];
                a[mi][2] = As[(mb    ) * ASTR + k8 + tig + 4];
                a[mi][3] = As[(mb + 8) * ASTR + k8 + tig + 4];
            }
#pragma unroll
            for (int nj = 0; nj < 4; nj++) {
                int nb = wn + nj * 8 + grp;
                unsigned b[2];
                b[0] = Bs[(k8 + tig) * BSTR + nb];
                b[1] = Bs[(k8 + tig + 4) * BSTR + nb];
                mma8(acc[0][nj], a[0], b);
                mma8(acc[1][nj], a[1], b);
            }
        }

        if (nxt) {
            int sn = s ^ 1;
            unsigned* An = sA + (size_t)sn * BM * ASTR;
            unsigned* Bn = sB + (size_t)sn * BK * BSTR;
#pragma unroll
            for (int p = 0; p < 4; p++)
                *(uint4*)&An[(size_t)(a_m + p * 32) * ASTR + a_k] = rtf4(pa[p]);
#pragma unroll
            for (int p = 0; p < 2; p++) {
                int k = b_k + p * 16;
                *(uint4*)&Bn[(size_t)k * BSTR + b_n] = rtf4(pb[p]);
            }
        }
        __syncthreads();
    }

#pragma unroll
    for (int mi = 0; mi < 2; mi++) {
#pragma unroll
        for (int nj = 0; nj < 4; nj++) {
            int mloc = wm + mi * 16 + grp;
            int ncol = n0 + wn + nj * 8 + tig * 2;
#pragma unroll
            for (int h = 0; h < 2; h++) {
                int ml = mloc + h * 8;
                int mr = m0 + ml;
                if (mr < cnt) {
                    int   t = toks[ml];
                    float w = wts[ml];
                    float* dst = out + (size_t)t * NH + ncol;
                    asm volatile("red.global.add.v2.f32 [%0], {%1,%2};"
                                 :: "l"(dst), "f"(w * acc[mi][nj][2*h]),
                                    "f"(w * acc[mi][nj][2*h + 1]) : "memory");
                }
            }
        }
    }
}

// ---------------- launch ----------------
extern "C" void kernel_launch(void* const* d_in, const int* in_sizes, int n_in,
                              void* d_out, int out_size)
{
    const float* hidden = (const float*)d_in[0];
    const int*   idx    = (const int*)  d_in[1];
    const float* topw   = (const float*)d_in[2];
    const float* gate_w = (const float*)d_in[3];
    const float* up_w   = (const float*)d_in[4];
    const float* down_w = (const float*)d_in[5];
    float* out = (float*)d_out;

    int smem1 = (A_WORDS + 2 * B_WORDS) * 4 + BM * 4;
    int smem2 = (A_WORDS + B_WORDS) * 4 + BM * 8;
    static int configured = 0;
    if (!configured) {
        cudaFuncSetAttribute(k_gemm1, cudaFuncAttributeMaxDynamicSharedMemorySize, smem1);
        cudaFuncSetAttribute(k_gemm2, cudaFuncAttributeMaxDynamicSharedMemorySize, smem2);
        configured = 1;
    }

    k_route<<<1, 1024>>>(idx, topw);
    k_zero<<<(NT * NH / 4) / 256, 256>>>(out);

    dim3 g1(NI / BN, NP / BM, NE);
    k_gemm1<<<g1, 256, smem1>>>(hidden, gate_w, up_w);

    dim3 g2(NH / BN, NP / BM, NE);
    k_gemm2<<<g2, 256, smem2>>>(down_w, out);
}

// round 11
// speedup vs baseline: 1.5228x; 1.0611x over previous
#include <cuda_runtime.h>
#include <math.h>

#define NT 2048
#define NH 2048
#define NI 1408
#define NE 8
#define TK 2
#define NP (NT*TK)

#define BM   128
#define BN   64
#define BK   32
#define ASTR 36    // [m][k], %32==4 -> A-frag reads hit banks 4*grp+tig (bijective)
#define BSTR 72    // [k][n], %32==8 -> B-frag reads hit banks 8*tig+grp (bijective)

// ---------------- scratch ----------------
__device__ int   g_cnt[NE];
__device__ int   g_off[NE + 1];
__device__ int   g_tok[NP];
__device__ float g_wt[NP];
__device__ float g_act[(size_t)NP * NI];

// ---------------- fused routing (one block) ----------------
__global__ __launch_bounds__(1024) void k_route(
    const int* __restrict__ idx, const float* __restrict__ w)
{
    __shared__ int scnt[NE], soff[NE], sfill[NE];
    int tid = threadIdx.x;
    if (tid < NE) { scnt[tid] = 0; sfill[tid] = 0; }
    __syncthreads();
    int my_e[4];
#pragma unroll
    for (int j = 0; j < 4; j++) {
        int i = tid + j * 1024;
        my_e[j] = idx[i];
        atomicAdd(&scnt[my_e[j]], 1);
    }
    __syncthreads();
    if (tid == 0) {
        int s = 0;
        for (int e = 0; e < NE; e++) {
            soff[e] = s; g_off[e] = s; g_cnt[e] = scnt[e]; s += scnt[e];
        }
        g_off[NE] = s;
    }
    __syncthreads();
#pragma unroll
    for (int j = 0; j < 4; j++) {
        int i = tid + j * 1024;
        int e = my_e[j];
        int pos = soff[e] + atomicAdd(&sfill[e], 1);
        g_tok[pos] = i / TK;
        g_wt[pos]  = w[i];
    }
}

__global__ void k_zero(float* __restrict__ out) {
    int i = blockIdx.x * blockDim.x + threadIdx.x;
    ((float4*)out)[i] = make_float4(0.f, 0.f, 0.f, 0.f);
}

// ---------------- tf32 helpers ----------------
__device__ __forceinline__ unsigned rtf(float f) {
    return __float_as_uint(f) + 0x1000u;
}
__device__ __forceinline__ uint4 rtf4(float4 v) {
    uint4 r;
    r.x = rtf(v.x); r.y = rtf(v.y); r.z = rtf(v.z); r.w = rtf(v.w);
    return r;
}
__device__ __forceinline__ void mma8(float* c, const unsigned* a, const unsigned* b) {
    asm volatile(
        "mma.sync.aligned.m16n8k8.row.col.f32.tf32.tf32.f32 "
        "{%0,%1,%2,%3},{%4,%5,%6,%7},{%8,%9},{%0,%1,%2,%3};"
        : "+f"(c[0]), "+f"(c[1]), "+f"(c[2]), "+f"(c[3])
        : "r"(a[0]), "r"(a[1]), "r"(a[2]), "r"(a[3]), "r"(b[0]), "r"(b[1]));
}

#define A_WORDS (2 * BM * ASTR)
#define B_WORDS (2 * BK * BSTR)

// ---------------- GEMM1: act = silu(X Wg) * (X Wu) ----------------
__global__ __launch_bounds__(256, 2) void k_gemm1(
    const float* __restrict__ hidden,
    const float* __restrict__ gate_w,
    const float* __restrict__ up_w)
{
    extern __shared__ unsigned sm[];
    unsigned* sA  = sm;
    unsigned* sBg = sA + A_WORDS;
    unsigned* sBu = sBg + B_WORDS;
    int* toks = (int*)(sBu + B_WORDS);

    int e = blockIdx.z, cnt = g_cnt[e];
    int m0 = blockIdx.y * BM;
    if (m0 >= cnt) return;
    int base = g_off[e];
    int n0 = blockIdx.x * BN;
    int tid = threadIdx.x;

    if (tid < BM) {
        int m = m0 + tid;
        toks[tid] = (m < cnt) ? g_tok[base + m] : g_tok[base];
    }
    __syncthreads();

    const float* gp = gate_w + (size_t)e * NH * NI;
    const float* up = up_w   + (size_t)e * NH * NI;

    int a_m = tid >> 3, a_k = (tid & 7) << 2;
    int b_k = tid >> 4, b_n = (tid & 15) << 2;

    size_t arow[4];
#pragma unroll
    for (int p = 0; p < 4; p++) arow[p] = (size_t)toks[a_m + p * 32] * NH;

#pragma unroll
    for (int p = 0; p < 4; p++) {
        float4 v = *(const float4*)(hidden + arow[p] + a_k);
        *(uint4*)&sA[(size_t)(a_m + p * 32) * ASTR + a_k] = rtf4(v);
    }
#pragma unroll
    for (int p = 0; p < 2; p++) {
        int k = b_k + p * 16;
        float4 vg = *(const float4*)(gp + (size_t)k * NI + n0 + b_n);
        float4 vu = *(const float4*)(up + (size_t)k * NI + n0 + b_n);
        *(uint4*)&sBg[(size_t)k * BSTR + b_n] = rtf4(vg);
        *(uint4*)&sBu[(size_t)k * BSTR + b_n] = rtf4(vu);
    }
    __syncthreads();

    int lane = tid & 31, wid = tid >> 5;
    int wm = (wid & 3) * 32, wn = (wid >> 2) * 32;
    int grp = lane >> 2, tig = lane & 3;

    float accg[2][4][4] = {}, accu[2][4][4] = {};
    float4 pa[4], pg[2], pu[2];

    for (int k0 = 0; k0 < NH; k0 += BK) {
        int s = (k0 / BK) & 1;
        bool nxt = (k0 + BK) < NH;
        if (nxt) {
            int kn = k0 + BK;
#pragma unroll
            for (int p = 0; p < 4; p++)
                pa[p] = *(const float4*)(hidden + arow[p] + kn + a_k);
#pragma unroll
            for (int p = 0; p < 2; p++) {
                int k = b_k + p * 16;
                pg[p] = *(const float4*)(gp + (size_t)(kn + k) * NI + n0 + b_n);
                pu[p] = *(const float4*)(up + (size_t)(kn + k) * NI + n0 + b_n);
            }
        }

        const unsigned* As = sA  + (size_t)s * BM * ASTR;
        const unsigned* Bg = sBg + (size_t)s * BK * BSTR;
        const unsigned* Bu = sBu + (size_t)s * BK * BSTR;

#pragma unroll
        for (int kk = 0; kk < 4; kk++) {
            int k8 = kk * 8;
            unsigned a[2][4];
#pragma unroll
            for (int mi = 0; mi < 2; mi++) {
                int mb = wm + mi * 16 + grp;
                a[mi][0] = As[(mb    ) * ASTR + k8 + tig    ];
                a[mi][1] = As[(mb + 8) * ASTR + k8 + tig    ];
                a[mi][2] = As[(mb    ) * ASTR + k8 + tig + 4];
                a[mi][3] = As[(mb + 8) * ASTR + k8 + tig + 4];
            }
#pragma unroll
            for (int nj = 0; nj < 4; nj++) {
                int nb = wn + nj * 8 + grp;
                unsigned b[2];
                b[0] = Bg[(k8 + tig) * BSTR + nb];
                b[1] = Bg[(k8 + tig + 4) * BSTR + nb];
                mma8(accg[0][nj], a[0], b);
                mma8(accg[1][nj], a[1], b);
                b[0] = Bu[(k8 + tig) * BSTR + nb];
                b[1] = Bu[(k8 + tig + 4) * BSTR + nb];
                mma8(accu[0][nj], a[0], b);
                mma8(accu[1][nj], a[1], b);
            }
        }

        if (nxt) {
            int sn = s ^ 1;
            unsigned* An  = sA  + (size_t)sn * BM * ASTR;
            unsigned* Bgn = sBg + (size_t)sn * BK * BSTR;
            unsigned* Bun = sBu + (size_t)sn * BK * BSTR;
#pragma unroll
            for (int p = 0; p < 4; p++)
                *(uint4*)&An[(size_t)(a_m + p * 32) * ASTR + a_k] = rtf4(pa[p]);
#pragma unroll
            for (int p = 0; p < 2; p++) {
                int k = b_k + p * 16;
                *(uint4*)&Bgn[(size_t)k * BSTR + b_n] = rtf4(pg[p]);
                *(uint4*)&Bun[(size_t)k * BSTR + b_n] = rtf4(pu[p]);
            }
        }
        __syncthreads();
    }

#pragma unroll
    for (int mi = 0; mi < 2; mi++) {
#pragma unroll
        for (int nj = 0; nj < 4; nj++) {
            int mrow = wm + mi * 16 + grp;
            int ncol = n0 + wn + nj * 8 + tig * 2;
#pragma unroll
            for (int h = 0; h < 2; h++) {
                int mr = m0 + mrow + h * 8;
                if (mr < cnt) {
                    float g0 = accg[mi][nj][2*h],     u0 = accu[mi][nj][2*h];
                    float g1 = accg[mi][nj][2*h + 1], u1 = accu[mi][nj][2*h + 1];
                    float2 v;
                    v.x = (g0 / (1.f + __expf(-g0))) * u0;
                    v.y = (g1 / (1.f + __expf(-g1))) * u1;
                    *(float2*)(g_act + (size_t)(base + mr) * NI + ncol) = v;
                }
            }
        }
    }
}

// ---------------- GEMM2: out[token] += wt * (act . Wd) ----------------
// Dual-N: one CTA covers two 64-wide N-blocks (n0, n0+64) sharing A fragments,
// same structure/register shape as k_gemm1 (proven at launch_bounds(256,2)).
__global__ __launch_bounds__(256, 2) void k_gemm2(
    const float* __restrict__ down_w,
    float* __restrict__ out)
{
    extern __shared__ unsigned sm[];
    unsigned* sA  = sm;
    unsigned* sB0 = sA + A_WORDS;
    unsigned* sB1 = sB0 + B_WORDS;
    int*   toks = (int*)(sB1 + B_WORDS);
    float* wts  = (float*)(toks + BM);

    int e = blockIdx.z, cnt = g_cnt[e];
    int m0 = blockIdx.y * BM;
    if (m0 >= cnt) return;
    int base = g_off[e];
    int n0 = blockIdx.x * (2 * BN);
    int tid = threadIdx.x;

    if (tid < BM) {
        int m = m0 + tid;
        toks[tid] = (m < cnt) ? g_tok[base + m] : 0;
        wts[tid]  = (m < cnt) ? g_wt[base + m] : 0.f;
    }
    __syncthreads();

    const float* dp = down_w + (size_t)e * NI * NH;

    int a_m = tid >> 3, a_k = (tid & 7) << 2;
    int b_k = tid >> 4, b_n = (tid & 15) << 2;

    size_t arow[4];
#pragma unroll
    for (int p = 0; p < 4; p++) {
        int m = m0 + a_m + p * 32;
        arow[p] = (size_t)(base + (m < cnt ? m : m0)) * NI;
    }

#pragma unroll
    for (int p = 0; p < 4; p++) {
        float4 v = *(const float4*)(g_act + arow[p] + a_k);
        *(uint4*)&sA[(size_t)(a_m + p * 32) * ASTR + a_k] = rtf4(v);
    }
#pragma unroll
    for (int p = 0; p < 2; p++) {
        int k = b_k + p * 16;
        float4 v0 = *(const float4*)(dp + (size_t)k * NH + n0 + b_n);
        float4 v1 = *(const float4*)(dp + (size_t)k * NH + n0 + 64 + b_n);
        *(uint4*)&sB0[(size_t)k * BSTR + b_n] = rtf4(v0);
        *(uint4*)&sB1[(size_t)k * BSTR + b_n] = rtf4(v1);
    }
    __syncthreads();

    int lane = tid & 31, wid = tid >> 5;
    int wm = (wid & 3) * 32, wn = (wid >> 2) * 32;
    int grp = lane >> 2, tig = lane & 3;

    float acc0[2][4][4] = {}, acc1[2][4][4] = {};
    float4 pa[4], pb0[2], pb1[2];

    for (int k0 = 0; k0 < NI; k0 += BK) {
        int s = (k0 / BK) & 1;
        bool nxt = (k0 + BK) < NI;
        if (nxt) {
            int kn = k0 + BK;
#pragma unroll
            for (int p = 0; p < 4; p++)
                pa[p] = *(const float4*)(g_act + arow[p] + kn + a_k);
#pragma unroll
            for (int p = 0; p < 2; p++) {
                int k = b_k + p * 16;
                pb0[p] = *(const float4*)(dp + (size_t)(kn + k) * NH + n0 + b_n);
                pb1[p] = *(const float4*)(dp + (size_t)(kn + k) * NH + n0 + 64 + b_n);
            }
        }

        const unsigned* As = sA  + (size_t)s * BM * ASTR;
        const unsigned* B0 = sB0 + (size_t)s * BK * BSTR;
        const unsigned* B1 = sB1 + (size_t)s * BK * BSTR;

#pragma unroll
        for (int kk = 0; kk < 4; kk++) {
            int k8 = kk * 8;
            unsigned a[2][4];
#pragma unroll
            for (int mi = 0; mi < 2; mi++) {
                int mb = wm + mi * 16 + grp;
                a[mi][0] = As[(mb    ) * ASTR + k8 + tig    ];
                a[mi][1] = As[(mb + 8) * ASTR + k8 + tig    ];
                a[mi][2] = As[(mb    ) * ASTR + k8 + tig + 4];
                a[mi][3] = As[(mb + 8) * ASTR + k8 + tig + 4];
            }
#pragma unroll
            for (int nj = 0; nj < 4; nj++) {
                int nb = wn + nj * 8 + grp;
                unsigned b[2];
                b[0] = B0[(k8 + tig) * BSTR + nb];
                b[1] = B0[(k8 + tig + 4) * BSTR + nb];
                mma8(acc0[0][nj], a[0], b);
                mma8(acc0[1][nj], a[1], b);
                b[0] = B1[(k8 + tig) * BSTR + nb];
                b[1] = B1[(k8 + tig + 4) * BSTR + nb];
                mma8(acc1[0][nj], a[0], b);
                mma8(acc1[1][nj], a[1], b);
            }
        }

        if (nxt) {
            int sn = s ^ 1;
            unsigned* An = sA  + (size_t)sn * BM * ASTR;
            unsigned* Bn0 = sB0 + (size_t)sn * BK * BSTR;
            unsigned* Bn1 = sB1 + (size_t)sn * BK * BSTR;
#pragma unroll
            for (int p = 0; p < 4; p++)
                *(uint4*)&An[(size_t)(a_m + p * 32) * ASTR + a_k] = rtf4(pa[p]);
#pragma unroll
            for (int p = 0; p < 2; p++) {
                int k = b_k + p * 16;
                *(uint4*)&Bn0[(size_t)k * BSTR + b_n] = rtf4(pb0[p]);
                *(uint4*)&Bn1[(size_t)k * BSTR + b_n] = rtf4(pb1[p]);
            }
        }
        __syncthreads();
    }

#pragma unroll
    for (int mi = 0; mi < 2; mi++) {
#pragma unroll
        for (int nj = 0; nj < 4; nj++) {
            int mloc = wm + mi * 16 + grp;
            int ncol = n0 + wn + nj * 8 + tig * 2;
#pragma unroll
            for (int h = 0; h < 2; h++) {
                int ml = mloc + h * 8;
                int mr = m0 + ml;
                if (mr < cnt) {
                    int   t = toks[ml];
                    float w = wts[ml];
                    float* dst = out + (size_t)t * NH + ncol;
                    asm volatile("red.global.add.v2.f32 [%0], {%1,%2};"
                                 :: "l"(dst), "f"(w * acc0[mi][nj][2*h]),
                                    "f"(w * acc0[mi][nj][2*h + 1]) : "memory");
                    asm volatile("red.global.add.v2.f32 [%0], {%1,%2};"
                                 :: "l"(dst + 64), "f"(w * acc1[mi][nj][2*h]),
                                    "f"(w * acc1[mi][nj][2*h + 1]) : "memory");
                }
            }
        }
    }
}

// ---------------- launch ----------------
extern "C" void kernel_launch(void* const* d_in, const int* in_sizes, int n_in,
                              void* d_out, int out_size)
{
    const float* hidden = (const float*)d_in[0];
    const int*   idx    = (const int*)  d_in[1];
    const float* topw   = (const float*)d_in[2];
    const float* gate_w = (const float*)d_in[3];
    const float* up_w   = (const float*)d_in[4];
    const float* down_w = (const float*)d_in[5];
    float* out = (float*)d_out;

    int smem1 = (A_WORDS + 2 * B_WORDS) * 4 + BM * 4;
    int smem2 = (A_WORDS + 2 * B_WORDS) * 4 + BM * 8;
    static int configured = 0;
    if (!configured) {
        cudaFuncSetAttribute(k_gemm1, cudaFuncAttributeMaxDynamicSharedMemorySize, smem1);
        cudaFuncSetAttribute(k_gemm2, cudaFuncAttributeMaxDynamicSharedMemorySize, smem2);
        configured = 1;
    }

    k_route<<<1, 1024>>>(idx, topw);
    k_zero<<<(NT * NH / 4) / 256, 256>>>(out);

    dim3 g1(NI / BN, NP / BM, NE);
    k_gemm1<<<g1, 256, smem1>>>(hidden, gate_w, up_w);

    dim3 g2(NH / (2 * BN), NP / BM, NE);
    k_gemm2<<<g2, 256, smem2>>>(down_w, out);
}

// round 12
// speedup vs baseline: 1.9309x; 1.2679x over previous
#include <cuda_runtime.h>
#include <cuda_fp16.h>
#include <math.h>

#define NT 2048
#define NH 2048
#define NI 1408
#define NE 8
#define TK 2
#define NP (NT*TK)

#define BM 128
#define BN 64
#define BK 32
// A: [m][k/2] fp16x2 words, 16 data words + 4 pad -> stride 20 (20%32=20; banks 20*grp+tig bijective)
#define AR 20
// B: [k/2][n] fp16x2 words, 64 data + 8 pad -> stride 72 (72%32=8; banks 8*tig+grp bijective)
#define BR 72

#define A_WORDS (2 * BM * AR)     // double buffered
#define B_WORDS (2 * 16 * BR)

// ---------------- scratch ----------------
__device__ int      g_cnt[NE];
__device__ int      g_off[NE + 1];
__device__ int      g_tok[NP];
__device__ float    g_wt[NP];
__device__ unsigned g_acth[(size_t)NP * NI / 2];   // fp16x2 activations (11.5 MB)

// ---------------- fused routing ----------------
__global__ __launch_bounds__(1024) void k_route(
    const int* __restrict__ idx, const float* __restrict__ w)
{
    __shared__ int scnt[NE], soff[NE], sfill[NE];
    int tid = threadIdx.x;
    if (tid < NE) { scnt[tid] = 0; sfill[tid] = 0; }
    __syncthreads();
    int my_e[4];
#pragma unroll
    for (int j = 0; j < 4; j++) {
        int i = tid + j * 1024;
        my_e[j] = idx[i];
        atomicAdd(&scnt[my_e[j]], 1);
    }
    __syncthreads();
    if (tid == 0) {
        int s = 0;
        for (int e = 0; e < NE; e++) {
            soff[e] = s; g_off[e] = s; g_cnt[e] = scnt[e]; s += scnt[e];
        }
        g_off[NE] = s;
    }
    __syncthreads();
#pragma unroll
    for (int j = 0; j < 4; j++) {
        int i = tid + j * 1024;
        int e = my_e[j];
        int pos = soff[e] + atomicAdd(&sfill[e], 1);
        g_tok[pos] = i / TK;
        g_wt[pos]  = w[i];
    }
}

__global__ void k_zero(float* __restrict__ out) {
    int i = blockIdx.x * blockDim.x + threadIdx.x;
    ((float4*)out)[i] = make_float4(0.f, 0.f, 0.f, 0.f);
}

// ---------------- fp16 helpers ----------------
__device__ __forceinline__ unsigned hpack(float lo, float hi) {
    __half2 h = __floats2half2_rn(lo, hi);   // x=lo -> low 16 bits
    return *(unsigned*)&h;
}
// pack two row-float4s (rows k, k+1) into 4 fp16x2 words: w[j] = {r0[j], r1[j]}
__device__ __forceinline__ uint4 hpack_rows(float4 r0, float4 r1) {
    uint4 w;
    w.x = hpack(r0.x, r1.x); w.y = hpack(r0.y, r1.y);
    w.z = hpack(r0.z, r1.z); w.w = hpack(r0.w, r1.w);
    return w;
}
// pack 8 consecutive-k floats (two float4) into 4 words: {f0,f1},{f2,f3},...
__device__ __forceinline__ uint4 hpack_k(float4 a, float4 b) {
    uint4 w;
    w.x = hpack(a.x, a.y); w.y = hpack(a.z, a.w);
    w.z = hpack(b.x, b.y); w.w = hpack(b.z, b.w);
    return w;
}
__device__ __forceinline__ void mma16(float* c, const unsigned* a, const unsigned* b) {
    asm volatile(
        "mma.sync.aligned.m16n8k16.row.col.f32.f16.f16.f32 "
        "{%0,%1,%2,%3},{%4,%5,%6,%7},{%8,%9},{%0,%1,%2,%3};"
        : "+f"(c[0]), "+f"(c[1]), "+f"(c[2]), "+f"(c[3])
        : "r"(a[0]), "r"(a[1]), "r"(a[2]), "r"(a[3]), "r"(b[0]), "r"(b[1]));
}

// ---------------- GEMM1: act = silu(X Wg) * (X Wu) ----------------
__global__ __launch_bounds__(256, 2) void k_gemm1(
    const float* __restrict__ hidden,
    const float* __restrict__ gate_w,
    const float* __restrict__ up_w)
{
    extern __shared__ unsigned sm[];
    unsigned* sA  = sm;                 // [2][128][AR]
    unsigned* sBg = sA + A_WORDS;       // [2][16][BR]
    unsigned* sBu = sBg + B_WORDS;
    int* toks = (int*)(sBu + B_WORDS);

    int e = blockIdx.z, cnt = g_cnt[e];
    int m0 = blockIdx.y * BM;
    if (m0 >= cnt) return;
    int base = g_off[e];
    int n0 = blockIdx.x * BN;
    int tid = threadIdx.x;

    if (tid < BM) {
        int m = m0 + tid;
        toks[tid] = (m < cnt) ? g_tok[base + m] : g_tok[base];
    }
    __syncthreads();

    const float* gp = gate_w + (size_t)e * NH * NI;
    const float* up = up_w   + (size_t)e * NH * NI;

    // A: 2 threads/row, 16 fp32 each
    int a_m = tid >> 1, a_k = (tid & 1) << 4;
    const float* aSrc = hidden + (size_t)toks[a_m] * NH + a_k;
    unsigned* aDstBase = sA + a_m * AR + (a_k >> 1);
    // B: thread -> (k2, 4 n's); source rows 2*k2, 2*k2+1
    int b_k2 = tid >> 4, b_n4 = (tid & 15) << 2;
    const float* gSrc = gp + (size_t)(2 * b_k2) * NI + n0 + b_n4;
    const float* uSrc = up + (size_t)(2 * b_k2) * NI + n0 + b_n4;
    unsigned bOff = b_k2 * BR + b_n4;

    // prologue (buffer 0)
    {
        float4 va0 = *(const float4*)(aSrc);
        float4 va1 = *(const float4*)(aSrc + 4);
        float4 va2 = *(const float4*)(aSrc + 8);
        float4 va3 = *(const float4*)(aSrc + 12);
        *(uint4*)(aDstBase)     = hpack_k(va0, va1);
        *(uint4*)(aDstBase + 4) = hpack_k(va2, va3);
        float4 g0 = *(const float4*)(gSrc);
        float4 g1 = *(const float4*)(gSrc + NI);
        float4 u0 = *(const float4*)(uSrc);
        float4 u1 = *(const float4*)(uSrc + NI);
        *(uint4*)(sBg + bOff) = hpack_rows(g0, g1);
        *(uint4*)(sBu + bOff) = hpack_rows(u0, u1);
    }
    __syncthreads();

    int lane = tid & 31, wid = tid >> 5;
    int wm = (wid & 3) * 32, wn = (wid >> 2) * 32;
    int grp = lane >> 2, tig = lane & 3;

    float accg[2][4][4] = {}, accu[2][4][4] = {};
    float4 pa[4], pg[2], pu[2];

    for (int k0 = 0; k0 < NH; k0 += BK) {
        int s = (k0 / BK) & 1;
        bool nxt = (k0 + BK) < NH;
        if (nxt) {
            int kn = k0 + BK;
            pa[0] = *(const float4*)(aSrc + kn);
            pa[1] = *(const float4*)(aSrc + kn + 4);
            pa[2] = *(const float4*)(aSrc + kn + 8);
            pa[3] = *(const float4*)(aSrc + kn + 12);
            pg[0] = *(const float4*)(gSrc + (size_t)kn * NI);
            pg[1] = *(const float4*)(gSrc + (size_t)(kn + 1) * NI);
            pu[0] = *(const float4*)(uSrc + (size_t)kn * NI);
            pu[1] = *(const float4*)(uSrc + (size_t)(kn + 1) * NI);
        }

        const unsigned* As = sA  + s * BM * AR;
        const unsigned* Bg = sBg + s * 16 * BR;
        const unsigned* Bu = sBu + s * 16 * BR;

#pragma unroll
        for (int kk = 0; kk < 2; kk++) {
            int k8 = kk * 8;
            unsigned a[2][4];
#pragma unroll
            for (int mi = 0; mi < 2; mi++) {
                int mb = wm + mi * 16 + grp;
                a[mi][0] = As[(mb    ) * AR + k8 + tig    ];
                a[mi][1] = As[(mb + 8) * AR + k8 + tig    ];
                a[mi][2] = As[(mb    ) * AR + k8 + tig + 4];
                a[mi][3] = As[(mb + 8) * AR + k8 + tig + 4];
            }
#pragma unroll
            for (int nj = 0; nj < 4; nj++) {
                int nb = wn + nj * 8 + grp;
                unsigned b[2];
                b[0] = Bg[(k8 + tig    ) * BR + nb];
                b[1] = Bg[(k8 + tig + 4) * BR + nb];
                mma16(accg[0][nj], a[0], b);
                mma16(accg[1][nj], a[1], b);
                b[0] = Bu[(k8 + tig    ) * BR + nb];
                b[1] = Bu[(k8 + tig + 4) * BR + nb];
                mma16(accu[0][nj], a[0], b);
                mma16(accu[1][nj], a[1], b);
            }
        }

        if (nxt) {
            int sn = s ^ 1;
            unsigned* An  = sA  + sn * BM * AR + a_m * AR + (a_k >> 1);
            unsigned* Bgn = sBg + sn * 16 * BR;
            unsigned* Bun = sBu + sn * 16 * BR;
            *(uint4*)(An)     = hpack_k(pa[0], pa[1]);
            *(uint4*)(An + 4) = hpack_k(pa[2], pa[3]);
            *(uint4*)(Bgn + bOff) = hpack_rows(pg[0], pg[1]);
            *(uint4*)(Bun + bOff) = hpack_rows(pu[0], pu[1]);
        }
        __syncthreads();
    }

    // epilogue: silu(g)*u -> g_acth (fp16x2)
#pragma unroll
    for (int mi = 0; mi < 2; mi++) {
#pragma unroll
        for (int nj = 0; nj < 4; nj++) {
            int mrow = wm + mi * 16 + grp;
            int ncol = n0 + wn + nj * 8 + tig * 2;
#pragma unroll
            for (int h = 0; h < 2; h++) {
                int mr = m0 + mrow + h * 8;
                if (mr < cnt) {
                    float g0 = accg[mi][nj][2*h],     u0 = accu[mi][nj][2*h];
                    float g1 = accg[mi][nj][2*h + 1], u1 = accu[mi][nj][2*h + 1];
                    float v0 = (g0 / (1.f + __expf(-g0))) * u0;
                    float v1 = (g1 / (1.f + __expf(-g1))) * u1;
                    g_acth[(size_t)(base + mr) * (NI / 2) + (ncol >> 1)] = hpack(v0, v1);
                }
            }
        }
    }
}

// ---------------- GEMM2: out[token] += wt * (act . Wd), dual-N ----------------
__global__ __launch_bounds__(256, 2) void k_gemm2(
    const float* __restrict__ down_w,
    float* __restrict__ out)
{
    extern __shared__ unsigned sm[];
    unsigned* sA  = sm;
    unsigned* sB0 = sA + A_WORDS;
    unsigned* sB1 = sB0 + B_WORDS;
    int*   toks = (int*)(sB1 + B_WORDS);
    float* wts  = (float*)(toks + BM);

    int e = blockIdx.z, cnt = g_cnt[e];
    int m0 = blockIdx.y * BM;
    if (m0 >= cnt) return;
    int base = g_off[e];
    int n0 = blockIdx.x * (2 * BN);
    int tid = threadIdx.x;

    if (tid < BM) {
        int m = m0 + tid;
        toks[tid] = (m < cnt) ? g_tok[base + m] : 0;
        wts[tid]  = (m < cnt) ? g_wt[base + m] : 0.f;
    }
    __syncthreads();

    const float* dp = down_w + (size_t)e * NI * NH;

    // A: pure fp16 copy; 2 threads/row, 8 words each
    int a_m = tid >> 1, a_w = (tid & 1) << 3;
    int am = m0 + a_m;
    const unsigned* aSrc = g_acth + (size_t)(base + (am < cnt ? am : m0)) * (NI / 2) + a_w;
    unsigned* aDstBase = sA + a_m * AR + a_w;
    // B: dual matrices at n0, n0+64
    int b_k2 = tid >> 4, b_n4 = (tid & 15) << 2;
    const float* bSrc0 = dp + (size_t)(2 * b_k2) * NH + n0 + b_n4;
    const float* bSrc1 = bSrc0 + 64;
    unsigned bOff = b_k2 * BR + b_n4;

    {
        *(uint4*)(aDstBase)     = *(const uint4*)(aSrc);
        *(uint4*)(aDstBase + 4) = *(const uint4*)(aSrc + 4);
        float4 v00 = *(const float4*)(bSrc0);
        float4 v01 = *(const float4*)(bSrc0 + NH);
        float4 v10 = *(const float4*)(bSrc1);
        float4 v11 = *(const float4*)(bSrc1 + NH);
        *(uint4*)(sB0 + bOff) = hpack_rows(v00, v01);
        *(uint4*)(sB1 + bOff) = hpack_rows(v10, v11);
    }
    __syncthreads();

    int lane = tid & 31, wid = tid >> 5;
    int wm = (wid & 3) * 32, wn = (wid >> 2) * 32;
    int grp = lane >> 2, tig = lane & 3;

    float acc0[2][4][4] = {}, acc1[2][4][4] = {};
    uint4 pa[2];
    float4 pb0[2], pb1[2];

    for (int k0 = 0; k0 < NI; k0 += BK) {
        int s = (k0 / BK) & 1;
        bool nxt = (k0 + BK) < NI;
        if (nxt) {
            int kn = k0 + BK;
            pa[0] = *(const uint4*)(aSrc + (kn >> 1));
            pa[1] = *(const uint4*)(aSrc + (kn >> 1) + 4);
            pb0[0] = *(const float4*)(bSrc0 + (size_t)kn * NH);
            pb0[1] = *(const float4*)(bSrc0 + (size_t)(kn + 1) * NH);
            pb1[0] = *(const float4*)(bSrc1 + (size_t)kn * NH);
            pb1[1] = *(const float4*)(bSrc1 + (size_t)(kn + 1) * NH);
        }

        const unsigned* As = sA  + s * BM * AR;
        const unsigned* B0 = sB0 + s * 16 * BR;
        const unsigned* B1 = sB1 + s * 16 * BR;

#pragma unroll
        for (int kk = 0; kk < 2; kk++) {
            int k8 = kk * 8;
            unsigned a[2][4];
#pragma unroll
            for (int mi = 0; mi < 2; mi++) {
                int mb = wm + mi * 16 + grp;
                a[mi][0] = As[(mb    ) * AR + k8 + tig    ];
                a[mi][1] = As[(mb + 8) * AR + k8 + tig    ];
                a[mi][2] = As[(mb    ) * AR + k8 + tig + 4];
                a[mi][3] = As[(mb + 8) * AR + k8 + tig + 4];
            }
#pragma unroll
            for (int nj = 0; nj < 4; nj++) {
                int nb = wn + nj * 8 + grp;
                unsigned b[2];
                b[0] = B0[(k8 + tig    ) * BR + nb];
                b[1] = B0[(k8 + tig + 4) * BR + nb];
                mma16(acc0[0][nj], a[0], b);
                mma16(acc0[1][nj], a[1], b);
                b[0] = B1[(k8 + tig    ) * BR + nb];
                b[1] = B1[(k8 + tig + 4) * BR + nb];
                mma16(acc1[0][nj], a[0], b);
                mma16(acc1[1][nj], a[1], b);
            }
        }

        if (nxt) {
            int sn = s ^ 1;
            unsigned* An  = sA  + sn * BM * AR + a_m * AR + a_w;
            unsigned* Bn0 = sB0 + sn * 16 * BR;
            unsigned* Bn1 = sB1 + sn * 16 * BR;
            *(uint4*)(An)     = pa[0];
            *(uint4*)(An + 4) = pa[1];
            *(uint4*)(Bn0 + bOff) = hpack_rows(pb0[0], pb0[1]);
            *(uint4*)(Bn1 + bOff) = hpack_rows(pb1[0], pb1[1]);
        }
        __syncthreads();
    }

#pragma unroll
    for (int mi = 0; mi < 2; mi++) {
#pragma unroll
        for (int nj = 0; nj < 4; nj++) {
            int mloc = wm + mi * 16 + grp;
            int ncol = n0 + wn + nj * 8 + tig * 2;
#pragma unroll
            for (int h = 0; h < 2; h++) {
                int ml = mloc + h * 8;
                int mr = m0 + ml;
                if (mr < cnt) {
                    int   t = toks[ml];
                    float w = wts[ml];
                    float* dst = out + (size_t)t * NH + ncol;
                    asm volatile("red.global.add.v2.f32 [%0], {%1,%2};"
                                 :: "l"(dst), "f"(w * acc0[mi][nj][2*h]),
                                    "f"(w * acc0[mi][nj][2*h + 1]) : "memory");
                    asm volatile("red.global.add.v2.f32 [%0], {%1,%2};"
                                 :: "l"(dst + 64), "f"(w * acc1[mi][nj][2*h]),
                                    "f"(w * acc1[mi][nj][2*h + 1]) : "memory");
                }
            }
        }
    }
}

// ---------------- launch ----------------
extern "C" void kernel_launch(void* const* d_in, const int* in_sizes, int n_in,
                              void* d_out, int out_size)
{
    const float* hidden = (const float*)d_in[0];
    const int*   idx    = (const int*)  d_in[1];
    const float* topw   = (const float*)d_in[2];
    const float* gate_w = (const float*)d_in[3];
    const float* up_w   = (const float*)d_in[4];
    const float* down_w = (const float*)d_in[5];
    float* out = (float*)d_out;

    int smem1 = (A_WORDS + 2 * B_WORDS) * 4 + BM * 4;
    int smem2 = (A_WORDS + 2 * B_WORDS) * 4 + BM * 8;
    static int configured = 0;
    if (!configured) {
        cudaFuncSetAttribute(k_gemm1, cudaFuncAttributeMaxDynamicSharedMemorySize, smem1);
        cudaFuncSetAttribute(k_gemm2, cudaFuncAttributeMaxDynamicSharedMemorySize, smem2);
        configured = 1;
    }

    k_route<<<1, 1024>>>(idx, topw);
    k_zero<<<(NT * NH / 4) / 256, 256>>>(out);

    dim3 g1(NI / BN, NP / BM, NE);
    k_gemm1<<<g1, 256, smem1>>>(hidden, gate_w, up_w);

    dim3 g2(NH / (2 * BN), NP / BM, NE);
    k_gemm2<<<g2, 256, smem2>>>(down_w, out);
}

// round 13
// speedup vs baseline: 1.9455x; 1.0076x over previous
#include <cuda_runtime.h>
#include <cuda_fp16.h>
#include <math.h>

#define NT 2048
#define NH 2048
#define NI 1408
#define NE 8
#define TK 2
#define NP (NT*TK)

#define BM 128
#define BN 64
#define BK 32
// A: [m][k/2] fp16x2 words, 16 data words + 4 pad -> stride 20
#define AR 20
// B: [k/2][n] fp16x2 words, 64 data + 8 pad -> stride 72 (72%32=8 conflict-free)
#define BR 72

#define A_WORDS (2 * BM * AR)     // double buffered
#define B_WORDS (2 * 16 * BR)

// ---------------- scratch ----------------
__device__ int      g_cnt[NE];
__device__ int      g_off[NE + 1];
__device__ int      g_tok[NP];
__device__ float    g_wt[NP];
__device__ unsigned g_acth[(size_t)NP * NI / 2];   // fp16x2 activations

// ---------------- fused routing ----------------
__global__ __launch_bounds__(1024) void k_route(
    const int* __restrict__ idx, const float* __restrict__ w)
{
    __shared__ int scnt[NE], soff[NE], sfill[NE];
    int tid = threadIdx.x;
    if (tid < NE) { scnt[tid] = 0; sfill[tid] = 0; }
    __syncthreads();
    int my_e[4];
#pragma unroll
    for (int j = 0; j < 4; j++) {
        int i = tid + j * 1024;
        my_e[j] = idx[i];
        atomicAdd(&scnt[my_e[j]], 1);
    }
    __syncthreads();
    if (tid == 0) {
        int s = 0;
        for (int e = 0; e < NE; e++) {
            soff[e] = s; g_off[e] = s; g_cnt[e] = scnt[e]; s += scnt[e];
        }
        g_off[NE] = s;
    }
    __syncthreads();
#pragma unroll
    for (int j = 0; j < 4; j++) {
        int i = tid + j * 1024;
        int e = my_e[j];
        int pos = soff[e] + atomicAdd(&sfill[e], 1);
        g_tok[pos] = i / TK;
        g_wt[pos]  = w[i];
    }
}

__global__ void k_zero(float* __restrict__ out) {
    int i = blockIdx.x * blockDim.x + threadIdx.x;
    ((float4*)out)[i] = make_float4(0.f, 0.f, 0.f, 0.f);
}

// ---------------- fp16 helpers ----------------
__device__ __forceinline__ unsigned hpack(float lo, float hi) {
    __half2 h = __floats2half2_rn(lo, hi);
    return *(unsigned*)&h;
}
__device__ __forceinline__ uint4 hpack_rows(float4 r0, float4 r1) {
    uint4 w;
    w.x = hpack(r0.x, r1.x); w.y = hpack(r0.y, r1.y);
    w.z = hpack(r0.z, r1.z); w.w = hpack(r0.w, r1.w);
    return w;
}
__device__ __forceinline__ uint4 hpack_k(float4 a, float4 b) {
    uint4 w;
    w.x = hpack(a.x, a.y); w.y = hpack(a.z, a.w);
    w.z = hpack(b.x, b.y); w.w = hpack(b.z, b.w);
    return w;
}
__device__ __forceinline__ void mma16(float* c, const unsigned* a, const unsigned* b) {
    asm volatile(
        "mma.sync.aligned.m16n8k16.row.col.f32.f16.f16.f32 "
        "{%0,%1,%2,%3},{%4,%5,%6,%7},{%8,%9},{%0,%1,%2,%3};"
        : "+f"(c[0]), "+f"(c[1]), "+f"(c[2]), "+f"(c[3])
        : "r"(a[0]), "r"(a[1]), "r"(a[2]), "r"(a[3]), "r"(b[0]), "r"(b[1]));
}

// ---------------- GEMM1: act = silu(X Wg) * (X Wu) ----------------
// Grid: x = M-tile (fastest -> consecutive CTAs share weight slice via L2), y = N-tile
__global__ __launch_bounds__(256, 2) void k_gemm1(
    const float* __restrict__ hidden,
    const float* __restrict__ gate_w,
    const float* __restrict__ up_w)
{
    extern __shared__ unsigned sm[];
    unsigned* sA  = sm;
    unsigned* sBg = sA + A_WORDS;
    unsigned* sBu = sBg + B_WORDS;
    int* toks = (int*)(sBu + B_WORDS);

    int e = blockIdx.z, cnt = g_cnt[e];
    int m0 = blockIdx.x * BM;
    if (m0 >= cnt) return;
    int base = g_off[e];
    int n0 = blockIdx.y * BN;
    int tid = threadIdx.x;

    if (tid < BM) {
        int m = m0 + tid;
        toks[tid] = (m < cnt) ? g_tok[base + m] : g_tok[base];
    }
    __syncthreads();

    const float* gp = gate_w + (size_t)e * NH * NI;
    const float* up = up_w   + (size_t)e * NH * NI;

    int a_m = tid >> 1, a_k = (tid & 1) << 4;
    const float* aSrc = hidden + (size_t)toks[a_m] * NH + a_k;
    unsigned* aDstBase = sA + a_m * AR + (a_k >> 1);
    int b_k2 = tid >> 4, b_n4 = (tid & 15) << 2;
    const float* gSrc = gp + (size_t)(2 * b_k2) * NI + n0 + b_n4;
    const float* uSrc = up + (size_t)(2 * b_k2) * NI + n0 + b_n4;
    unsigned bOff = b_k2 * BR + b_n4;

    {
        float4 va0 = *(const float4*)(aSrc);
        float4 va1 = *(const float4*)(aSrc + 4);
        float4 va2 = *(const float4*)(aSrc + 8);
        float4 va3 = *(const float4*)(aSrc + 12);
        *(uint4*)(aDstBase)     = hpack_k(va0, va1);
        *(uint4*)(aDstBase + 4) = hpack_k(va2, va3);
        float4 g0 = *(const float4*)(gSrc);
        float4 g1 = *(const float4*)(gSrc + NI);
        float4 u0 = *(const float4*)(uSrc);
        float4 u1 = *(const float4*)(uSrc + NI);
        *(uint4*)(sBg + bOff) = hpack_rows(g0, g1);
        *(uint4*)(sBu + bOff) = hpack_rows(u0, u1);
    }
    __syncthreads();

    int lane = tid & 31, wid = tid >> 5;
    int wm = (wid & 3) * 32, wn = (wid >> 2) * 32;
    int grp = lane >> 2, tig = lane & 3;

    float accg[2][4][4] = {}, accu[2][4][4] = {};
    float4 pa[4], pg[2], pu[2];

    for (int k0 = 0; k0 < NH; k0 += BK) {
        int s = (k0 / BK) & 1;
        bool nxt = (k0 + BK) < NH;
        if (nxt) {
            int kn = k0 + BK;
            pa[0] = *(const float4*)(aSrc + kn);
            pa[1] = *(const float4*)(aSrc + kn + 4);
            pa[2] = *(const float4*)(aSrc + kn + 8);
            pa[3] = *(const float4*)(aSrc + kn + 12);
            pg[0] = *(const float4*)(gSrc + (size_t)kn * NI);
            pg[1] = *(const float4*)(gSrc + (size_t)(kn + 1) * NI);
            pu[0] = *(const float4*)(uSrc + (size_t)kn * NI);
            pu[1] = *(const float4*)(uSrc + (size_t)(kn + 1) * NI);
        }

        const unsigned* As = sA  + s * BM * AR;
        const unsigned* Bg = sBg + s * 16 * BR;
        const unsigned* Bu = sBu + s * 16 * BR;

#pragma unroll
        for (int kk = 0; kk < 2; kk++) {
            int k8 = kk * 8;
            unsigned a[2][4];
#pragma unroll
            for (int mi = 0; mi < 2; mi++) {
                int mb = wm + mi * 16 + grp;
                a[mi][0] = As[(mb    ) * AR + k8 + tig    ];
                a[mi][1] = As[(mb + 8) * AR + k8 + tig    ];
                a[mi][2] = As[(mb    ) * AR + k8 + tig + 4];
                a[mi][3] = As[(mb + 8) * AR + k8 + tig + 4];
            }
#pragma unroll
            for (int nj = 0; nj < 4; nj++) {
                int nb = wn + nj * 8 + grp;
                unsigned b[2];
                b[0] = Bg[(k8 + tig    ) * BR + nb];
                b[1] = Bg[(k8 + tig + 4) * BR + nb];
                mma16(accg[0][nj], a[0], b);
                mma16(accg[1][nj], a[1], b);
                b[0] = Bu[(k8 + tig    ) * BR + nb];
                b[1] = Bu[(k8 + tig + 4) * BR + nb];
                mma16(accu[0][nj], a[0], b);
                mma16(accu[1][nj], a[1], b);
            }
        }

        if (nxt) {
            int sn = s ^ 1;
            unsigned* An  = sA  + sn * BM * AR + a_m * AR + (a_k >> 1);
            unsigned* Bgn = sBg + sn * 16 * BR;
            unsigned* Bun = sBu + sn * 16 * BR;
            *(uint4*)(An)     = hpack_k(pa[0], pa[1]);
            *(uint4*)(An + 4) = hpack_k(pa[2], pa[3]);
            *(uint4*)(Bgn + bOff) = hpack_rows(pg[0], pg[1]);
            *(uint4*)(Bun + bOff) = hpack_rows(pu[0], pu[1]);
        }
        __syncthreads();
    }

#pragma unroll
    for (int mi = 0; mi < 2; mi++) {
#pragma unroll
        for (int nj = 0; nj < 4; nj++) {
            int mrow = wm + mi * 16 + grp;
            int ncol = n0 + wn + nj * 8 + tig * 2;
#pragma unroll
            for (int h = 0; h < 2; h++) {
                int mr = m0 + mrow + h * 8;
                if (mr < cnt) {
                    float g0 = accg[mi][nj][2*h],     u0 = accu[mi][nj][2*h];
                    float g1 = accg[mi][nj][2*h + 1], u1 = accu[mi][nj][2*h + 1];
                    float v0 = (g0 / (1.f + __expf(-g0))) * u0;
                    float v1 = (g1 / (1.f + __expf(-g1))) * u1;
                    g_acth[(size_t)(base + mr) * (NI / 2) + (ncol >> 1)] = hpack(v0, v1);
                }
            }
        }
    }
}

// ---------------- GEMM2: out[token] += wt * (act . Wd), dual-N ----------------
// Grid: x = M-tile (fastest), y = N-pair tile
__global__ __launch_bounds__(256, 2) void k_gemm2(
    const float* __restrict__ down_w,
    float* __restrict__ out)
{
    extern __shared__ unsigned sm[];
    unsigned* sA  = sm;
    unsigned* sB0 = sA + A_WORDS;
    unsigned* sB1 = sB0 + B_WORDS;
    int*   toks = (int*)(sB1 + B_WORDS);
    float* wts  = (float*)(toks + BM);

    int e = blockIdx.z, cnt = g_cnt[e];
    int m0 = blockIdx.x * BM;
    if (m0 >= cnt) return;
    int base = g_off[e];
    int n0 = blockIdx.y * (2 * BN);
    int tid = threadIdx.x;

    if (tid < BM) {
        int m = m0 + tid;
        toks[tid] = (m < cnt) ? g_tok[base + m] : 0;
        wts[tid]  = (m < cnt) ? g_wt[base + m] : 0.f;
    }
    __syncthreads();

    const float* dp = down_w + (size_t)e * NI * NH;

    int a_m = tid >> 1, a_w = (tid & 1) << 3;
    int am = m0 + a_m;
    const unsigned* aSrc = g_acth + (size_t)(base + (am < cnt ? am : m0)) * (NI / 2) + a_w;
    unsigned* aDstBase = sA + a_m * AR + a_w;
    int b_k2 = tid >> 4, b_n4 = (tid & 15) << 2;
    const float* bSrc0 = dp + (size_t)(2 * b_k2) * NH + n0 + b_n4;
    const float* bSrc1 = bSrc0 + 64;
    unsigned bOff = b_k2 * BR + b_n4;

    {
        *(uint4*)(aDstBase)     = *(const uint4*)(aSrc);
        *(uint4*)(aDstBase + 4) = *(const uint4*)(aSrc + 4);
        float4 v00 = *(const float4*)(bSrc0);
        float4 v01 = *(const float4*)(bSrc0 + NH);
        float4 v10 = *(const float4*)(bSrc1);
        float4 v11 = *(const float4*)(bSrc1 + NH);
        *(uint4*)(sB0 + bOff) = hpack_rows(v00, v01);
        *(uint4*)(sB1 + bOff) = hpack_rows(v10, v11);
    }
    __syncthreads();

    int lane = tid & 31, wid = tid >> 5;
    int wm = (wid & 3) * 32, wn = (wid >> 2) * 32;
    int grp = lane >> 2, tig = lane & 3;

    float acc0[2][4][4] = {}, acc1[2][4][4] = {};
    uint4 pa[2];
    float4 pb0[2], pb1[2];

    for (int k0 = 0; k0 < NI; k0 += BK) {
        int s = (k0 / BK) & 1;
        bool nxt = (k0 + BK) < NI;
        if (nxt) {
            int kn = k0 + BK;
            pa[0] = *(const uint4*)(aSrc + (kn >> 1));
            pa[1] = *(const uint4*)(aSrc + (kn >> 1) + 4);
            pb0[0] = *(const float4*)(bSrc0 + (size_t)kn * NH);
            pb0[1] = *(const float4*)(bSrc0 + (size_t)(kn + 1) * NH);
            pb1[0] = *(const float4*)(bSrc1 + (size_t)kn * NH);
            pb1[1] = *(const float4*)(bSrc1 + (size_t)(kn + 1) * NH);
        }

        const unsigned* As = sA  + s * BM * AR;
        const unsigned* B0 = sB0 + s * 16 * BR;
        const unsigned* B1 = sB1 + s * 16 * BR;

#pragma unroll
        for (int kk = 0; kk < 2; kk++) {
            int k8 = kk * 8;
            unsigned a[2][4];
#pragma unroll
            for (int mi = 0; mi < 2; mi++) {
                int mb = wm + mi * 16 + grp;
                a[mi][0] = As[(mb    ) * AR + k8 + tig    ];
                a[mi][1] = As[(mb + 8) * AR + k8 + tig    ];
                a[mi][2] = As[(mb    ) * AR + k8 + tig + 4];
                a[mi][3] = As[(mb + 8) * AR + k8 + tig + 4];
            }
#pragma unroll
            for (int nj = 0; nj < 4; nj++) {
                int nb = wn + nj * 8 + grp;
                unsigned b[2];
                b[0] = B0[(k8 + tig    ) * BR + nb];
                b[1] = B0[(k8 + tig + 4) * BR + nb];
                mma16(acc0[0][nj], a[0], b);
                mma16(acc0[1][nj], a[1], b);
                b[0] = B1[(k8 + tig    ) * BR + nb];
                b[1] = B1[(k8 + tig + 4) * BR + nb];
                mma16(acc1[0][nj], a[0], b);
                mma16(acc1[1][nj], a[1], b);
            }
        }

        if (nxt) {
            int sn = s ^ 1;
            unsigned* An  = sA  + sn * BM * AR + a_m * AR + a_w;
            unsigned* Bn0 = sB0 + sn * 16 * BR;
            unsigned* Bn1 = sB1 + sn * 16 * BR;
            *(uint4*)(An)     = pa[0];
            *(uint4*)(An + 4) = pa[1];
            *(uint4*)(Bn0 + bOff) = hpack_rows(pb0[0], pb0[1]);
            *(uint4*)(Bn1 + bOff) = hpack_rows(pb1[0], pb1[1]);
        }
        __syncthreads();
    }

#pragma unroll
    for (int mi = 0; mi < 2; mi++) {
#pragma unroll
        for (int nj = 0; nj < 4; nj++) {
            int mloc = wm + mi * 16 + grp;
            int ncol = n0 + wn + nj * 8 + tig * 2;
#pragma unroll
            for (int h = 0; h < 2; h++) {
                int ml = mloc + h * 8;
                int mr = m0 + ml;
                if (mr < cnt) {
                    int   t = toks[ml];
                    float w = wts[ml];
                    float* dst = out + (size_t)t * NH + ncol;
                    asm volatile("red.global.add.v2.f32 [%0], {%1,%2};"
                                 :: "l"(dst), "f"(w * acc0[mi][nj][2*h]),
                                    "f"(w * acc0[mi][nj][2*h + 1]) : "memory");
                    asm volatile("red.global.add.v2.f32 [%0], {%1,%2};"
                                 :: "l"(dst + 64), "f"(w * acc1[mi][nj][2*h]),
                                    "f"(w * acc1[mi][nj][2*h + 1]) : "memory");
                }
            }
        }
    }
}

// ---------------- launch ----------------
extern "C" void kernel_launch(void* const* d_in, const int* in_sizes, int n_in,
                              void* d_out, int out_size)
{
    const float* hidden = (const float*)d_in[0];
    const int*   idx    = (const int*)  d_in[1];
    const float* topw   = (const float*)d_in[2];
    const float* gate_w = (const float*)d_in[3];
    const float* up_w   = (const float*)d_in[4];
    const float* down_w = (const float*)d_in[5];
    float* out = (float*)d_out;

    int smem1 = (A_WORDS + 2 * B_WORDS) * 4 + BM * 4;
    int smem2 = (A_WORDS + 2 * B_WORDS) * 4 + BM * 8;
    static int configured = 0;
    if (!configured) {
        cudaFuncSetAttribute(k_gemm1, cudaFuncAttributeMaxDynamicSharedMemorySize, smem1);
        cudaFuncSetAttribute(k_gemm2, cudaFuncAttributeMaxDynamicSharedMemorySize, smem2);
        configured = 1;
    }

    k_route<<<1, 1024>>>(idx, topw);
    k_zero<<<(NT * NH / 4) / 256, 256>>>(out);

    dim3 g1(NP / BM, NI / BN, NE);
    k_gemm1<<<g1, 256, smem1>>>(hidden, gate_w, up_w);

    dim3 g2(NP / BM, NH / (2 * BN), NE);
    k_gemm2<<<g2, 256, smem2>>>(down_w, out);
}

// round 14
// speedup vs baseline: 2.0744x; 1.0662x over previous
#include <cuda_runtime.h>
#include <cuda_fp16.h>
#include <math.h>

#define NT 2048
#define NH 2048
#define NI 1408
#define NE 8
#define TK 2
#define NP (NT*TK)

#define BM 128
#define BK 32
#define AR 20     // A [m][k/2] words + pad; rows 20 apart -> LDSM-free frag reads conflict-free
#define BR1 72    // gemm1 B [k/2][64n] + 8 pad (72%32=8 -> conflict-free)
#define BR2 136   // gemm2 B [k/2][128n] + 8 pad (136%32=8 -> conflict-free)

#define A_WORDS  (2 * BM * AR)      // 5120, double buffered
#define B1_WORDS (2 * 16 * BR1)     // 2304 per matrix
#define B2_WORDS (2 * 16 * BR2)     // 4352

// ---------------- scratch ----------------
__device__ int      g_cnt[NE];
__device__ int      g_off[NE + 1];
__device__ int      g_tok[NP];
__device__ float    g_wt[NP];
__device__ unsigned g_hidh[(size_t)NT * NH / 2];   // fp16x2 hidden (8 MB)
__device__ unsigned g_acth[(size_t)NP * NI / 2];   // fp16x2 activations (11.5 MB)

// ---------------- fused routing ----------------
__global__ __launch_bounds__(1024) void k_route(
    const int* __restrict__ idx, const float* __restrict__ w)
{
    __shared__ int scnt[NE], soff[NE], sfill[NE];
    int tid = threadIdx.x;
    if (tid < NE) { scnt[tid] = 0; sfill[tid] = 0; }
    __syncthreads();
    int my_e[4];
#pragma unroll
    for (int j = 0; j < 4; j++) {
        int i = tid + j * 1024;
        my_e[j] = idx[i];
        atomicAdd(&scnt[my_e[j]], 1);
    }
    __syncthreads();
    if (tid == 0) {
        int s = 0;
        for (int e = 0; e < NE; e++) {
            soff[e] = s; g_off[e] = s; g_cnt[e] = scnt[e]; s += scnt[e];
        }
        g_off[NE] = s;
    }
    __syncthreads();
#pragma unroll
    for (int j = 0; j < 4; j++) {
        int i = tid + j * 1024;
        int e = my_e[j];
        int pos = soff[e] + atomicAdd(&sfill[e], 1);
        g_tok[pos] = i / TK;
        g_wt[pos]  = w[i];
    }
}

// ---------------- fp16 helpers ----------------
__device__ __forceinline__ unsigned hpack(float lo, float hi) {
    __half2 h = __floats2half2_rn(lo, hi);
    return *(unsigned*)&h;
}
__device__ __forceinline__ uint4 hpack_rows(float4 r0, float4 r1) {
    uint4 w;
    w.x = hpack(r0.x, r1.x); w.y = hpack(r0.y, r1.y);
    w.z = hpack(r0.z, r1.z); w.w = hpack(r0.w, r1.w);
    return w;
}
__device__ __forceinline__ uint4 hpack_k(float4 a, float4 b) {
    uint4 w;
    w.x = hpack(a.x, a.y); w.y = hpack(a.z, a.w);
    w.z = hpack(b.x, b.y); w.w = hpack(b.z, b.w);
    return w;
}
__device__ __forceinline__ void mma16(float* c, const unsigned* a, const unsigned* b) {
    asm volatile(
        "mma.sync.aligned.m16n8k16.row.col.f32.f16.f16.f32 "
        "{%0,%1,%2,%3},{%4,%5,%6,%7},{%8,%9},{%0,%1,%2,%3};"
        : "+f"(c[0]), "+f"(c[1]), "+f"(c[2]), "+f"(c[3])
        : "r"(a[0]), "r"(a[1]), "r"(a[2]), "r"(a[3]), "r"(b[0]), "r"(b[1]));
}

// pre-round hidden to fp16 + zero output
__global__ void k_prep(const float* __restrict__ hidden, float* __restrict__ out) {
    int i = blockIdx.x * blockDim.x + threadIdx.x;   // 0 .. NT*NH/8-1
    float4 a = ((const float4*)hidden)[2 * i];
    float4 b = ((const float4*)hidden)[2 * i + 1];
    ((uint4*)g_hidh)[i] = hpack_k(a, b);
    ((float4*)out)[2 * i]     = make_float4(0.f, 0.f, 0.f, 0.f);
    ((float4*)out)[2 * i + 1] = make_float4(0.f, 0.f, 0.f, 0.f);
}

// ---------------- GEMM1: act = silu(X Wg) * (X Wu) ----------------
// CTA 128M x 64N x 2mat, 4 warps (2M x 2N), warp tile 64M x 32N x 2mat.
__global__ __launch_bounds__(128, 2) void k_gemm1(
    const float* __restrict__ gate_w,
    const float* __restrict__ up_w)
{
    extern __shared__ unsigned sm[];
    unsigned* sA  = sm;                 // [2][128][AR]
    unsigned* sBg = sA + A_WORDS;       // [2][16][BR1]
    unsigned* sBu = sBg + B1_WORDS;
    int* toks = (int*)(sBu + B1_WORDS);

    int e = blockIdx.x % NE, cnt = g_cnt[e];
    int m0 = blockIdx.z * BM;
    if (m0 >= cnt) return;
    int base = g_off[e];
    int n0 = blockIdx.y * 64;
    int tid = threadIdx.x;

    if (tid < BM) {
        int m = m0 + tid;
        toks[tid] = (m < cnt) ? g_tok[base + m] : g_tok[base];
    }
    __syncthreads();

    const float* gp = gate_w + (size_t)e * NH * NI;
    const float* up = up_w   + (size_t)e * NH * NI;

    // A staging: 1 thread per row, 4 uint4 fp16 copy per K-tile
    const unsigned* aSrc = g_hidh + (size_t)toks[tid] * (NH / 2);
    unsigned* aDst0 = sA + tid * AR;
    // B staging: 2 slots per matrix; slot s: idx = tid + 128s
    int k2a = tid >> 4,        n4a = (tid & 15) << 2;
    int k2b = (tid + 128) >> 4, n4b = ((tid + 128) & 15) << 2;
    const float* gA = gp + (size_t)(2 * k2a) * NI + n0 + n4a;
    const float* gB = gp + (size_t)(2 * k2b) * NI + n0 + n4b;
    const float* uA = up + (size_t)(2 * k2a) * NI + n0 + n4a;
    const float* uB = up + (size_t)(2 * k2b) * NI + n0 + n4b;
    unsigned bOffA = k2a * BR1 + n4a, bOffB = k2b * BR1 + n4b;

    // prologue
    {
        uint4 c0 = ((const uint4*)aSrc)[0], c1 = ((const uint4*)aSrc)[1];
        uint4 c2 = ((const uint4*)aSrc)[2], c3 = ((const uint4*)aSrc)[3];
        *(uint4*)(aDst0) = c0; *(uint4*)(aDst0 + 4) = c1;
        *(uint4*)(aDst0 + 8) = c2; *(uint4*)(aDst0 + 12) = c3;
        *(uint4*)(sBg + bOffA) = hpack_rows(*(const float4*)gA, *(const float4*)(gA + NI));
        *(uint4*)(sBg + bOffB) = hpack_rows(*(const float4*)gB, *(const float4*)(gB + NI));
        *(uint4*)(sBu + bOffA) = hpack_rows(*(const float4*)uA, *(const float4*)(uA + NI));
        *(uint4*)(sBu + bOffB) = hpack_rows(*(const float4*)uB, *(const float4*)(uB + NI));
    }
    __syncthreads();

    int lane = tid & 31, wid = tid >> 5;
    int wm = (wid & 1) * 64, wn = (wid >> 1) * 32;
    int grp = lane >> 2, tig = lane & 3;

    float accg[4][4][4] = {}, accu[4][4][4] = {};
    uint4 pa[4];
    float4 pg[4], pu[4];

    for (int k0 = 0; k0 < NH; k0 += BK) {
        int s = (k0 / BK) & 1;
        bool nxt = (k0 + BK) < NH;
        if (nxt) {
            int kn = k0 + BK;
            const unsigned* as = aSrc + (kn >> 1);
            pa[0] = ((const uint4*)as)[0]; pa[1] = ((const uint4*)as)[1];
            pa[2] = ((const uint4*)as)[2]; pa[3] = ((const uint4*)as)[3];
            pg[0] = *(const float4*)(gA + (size_t)kn * NI);
            pg[1] = *(const float4*)(gA + (size_t)(kn + 1) * NI);
            pg[2] = *(const float4*)(gB + (size_t)kn * NI);
            pg[3] = *(const float4*)(gB + (size_t)(kn + 1) * NI);
            pu[0] = *(const float4*)(uA + (size_t)kn * NI);
            pu[1] = *(const float4*)(uA + (size_t)(kn + 1) * NI);
            pu[2] = *(const float4*)(uB + (size_t)kn * NI);
            pu[3] = *(const float4*)(uB + (size_t)(kn + 1) * NI);
        }

        const unsigned* As = sA  + s * BM * AR;
        const unsigned* Bg = sBg + s * 16 * BR1;
        const unsigned* Bu = sBu + s * 16 * BR1;

#pragma unroll
        for (int kk = 0; kk < 2; kk++) {
            int k8 = kk * 8;
            unsigned a[4][4];
#pragma unroll
            for (int mi = 0; mi < 4; mi++) {
                int mb = wm + mi * 16 + grp;
                a[mi][0] = As[(mb    ) * AR + k8 + tig    ];
                a[mi][1] = As[(mb + 8) * AR + k8 + tig    ];
                a[mi][2] = As[(mb    ) * AR + k8 + tig + 4];
                a[mi][3] = As[(mb + 8) * AR + k8 + tig + 4];
            }
#pragma unroll
            for (int nj = 0; nj < 4; nj++) {
                int nb = wn + nj * 8 + grp;
                unsigned b[2];
                b[0] = Bg[(k8 + tig    ) * BR1 + nb];
                b[1] = Bg[(k8 + tig + 4) * BR1 + nb];
#pragma unroll
                for (int mi = 0; mi < 4; mi++) mma16(accg[mi][nj], a[mi], b);
                b[0] = Bu[(k8 + tig    ) * BR1 + nb];
                b[1] = Bu[(k8 + tig + 4) * BR1 + nb];
#pragma unroll
                for (int mi = 0; mi < 4; mi++) mma16(accu[mi][nj], a[mi], b);
            }
        }

        if (nxt) {
            int sn = s ^ 1;
            unsigned* An  = sA  + sn * BM * AR + tid * AR;
            unsigned* Bgn = sBg + sn * 16 * BR1;
            unsigned* Bun = sBu + sn * 16 * BR1;
            *(uint4*)(An) = pa[0]; *(uint4*)(An + 4) = pa[1];
            *(uint4*)(An + 8) = pa[2]; *(uint4*)(An + 12) = pa[3];
            *(uint4*)(Bgn + bOffA) = hpack_rows(pg[0], pg[1]);
            *(uint4*)(Bgn + bOffB) = hpack_rows(pg[2], pg[3]);
            *(uint4*)(Bun + bOffA) = hpack_rows(pu[0], pu[1]);
            *(uint4*)(Bun + bOffB) = hpack_rows(pu[2], pu[3]);
        }
        __syncthreads();
    }

    // epilogue: silu(g)*u -> g_acth
#pragma unroll
    for (int mi = 0; mi < 4; mi++) {
#pragma unroll
        for (int nj = 0; nj < 4; nj++) {
            int mrow = wm + mi * 16 + grp;
            int ncol = n0 + wn + nj * 8 + tig * 2;
#pragma unroll
            for (int h = 0; h < 2; h++) {
                int mr = m0 + mrow + h * 8;
                if (mr < cnt) {
                    float g0 = accg[mi][nj][2*h],     u0 = accu[mi][nj][2*h];
                    float g1 = accg[mi][nj][2*h + 1], u1 = accu[mi][nj][2*h + 1];
                    float v0 = (g0 / (1.f + __expf(-g0))) * u0;
                    float v1 = (g1 / (1.f + __expf(-g1))) * u1;
                    g_acth[(size_t)(base + mr) * (NI / 2) + (ncol >> 1)] = hpack(v0, v1);
                }
            }
        }
    }
}

// ---------------- GEMM2: out[token] += wt * (act . Wd) ----------------
// CTA 128M x 128N, 4 warps (2M x 2N), warp tile 64M x 64N.
__global__ __launch_bounds__(128, 2) void k_gemm2(
    const float* __restrict__ down_w,
    float* __restrict__ out)
{
    extern __shared__ unsigned sm[];
    unsigned* sA = sm;                  // [2][128][AR]
    unsigned* sB = sA + A_WORDS;        // [2][16][BR2]
    int*   toks = (int*)(sB + B2_WORDS);
    float* wts  = (float*)(toks + BM);

    int e = blockIdx.x % NE, cnt = g_cnt[e];
    int m0 = blockIdx.z * BM;
    if (m0 >= cnt) return;
    int base = g_off[e];
    int n0 = blockIdx.y * 128;
    int tid = threadIdx.x;

    if (tid < BM) {
        int m = m0 + tid;
        toks[tid] = (m < cnt) ? g_tok[base + m] : 0;
        wts[tid]  = (m < cnt) ? g_wt[base + m] : 0.f;
    }
    __syncthreads();

    const float* dp = down_w + (size_t)e * NI * NH;

    int am = m0 + tid;
    const unsigned* aSrc = g_acth + (size_t)(base + (am < cnt ? am : m0)) * (NI / 2);
    unsigned* aDst0 = sA + tid * AR;

    // B staging: 4 slots; slot s: idx = tid + 128s -> k2 = idx>>5, n4 = (idx&31)*4
    int k2s[4], n4s[4];
    unsigned bOffs[4];
#pragma unroll
    for (int s2 = 0; s2 < 4; s2++) {
        int idx = tid + 128 * s2;
        k2s[s2] = idx >> 5;
        n4s[s2] = (idx & 31) << 2;
        bOffs[s2] = k2s[s2] * BR2 + n4s[s2];
    }

    {
        uint4 c0 = ((const uint4*)aSrc)[0], c1 = ((const uint4*)aSrc)[1];
        uint4 c2 = ((const uint4*)aSrc)[2], c3 = ((const uint4*)aSrc)[3];
        *(uint4*)(aDst0) = c0; *(uint4*)(aDst0 + 4) = c1;
        *(uint4*)(aDst0 + 8) = c2; *(uint4*)(aDst0 + 12) = c3;
#pragma unroll
        for (int s2 = 0; s2 < 4; s2++) {
            const float* bs = dp + (size_t)(2 * k2s[s2]) * NH + n0 + n4s[s2];
            *(uint4*)(sB + bOffs[s2]) = hpack_rows(*(const float4*)bs, *(const float4*)(bs + NH));
        }
    }
    __syncthreads();

    int lane = tid & 31, wid = tid >> 5;
    int wm = (wid & 1) * 64, wn = (wid >> 1) * 64;
    int grp = lane >> 2, tig = lane & 3;

    float acc[4][8][4] = {};
    uint4 pa[4];
    float4 pb[8];

    for (int k0 = 0; k0 < NI; k0 += BK) {
        int s = (k0 / BK) & 1;
        bool nxt = (k0 + BK) < NI;
        if (nxt) {
            int kn = k0 + BK;
            const unsigned* as = aSrc + (kn >> 1);
            pa[0] = ((const uint4*)as)[0]; pa[1] = ((const uint4*)as)[1];
            pa[2] = ((const uint4*)as)[2]; pa[3] = ((const uint4*)as)[3];
#pragma unroll
            for (int s2 = 0; s2 < 4; s2++) {
                const float* bs = dp + (size_t)(kn + 2 * k2s[s2]) * NH + n0 + n4s[s2];
                pb[2*s2]     = *(const float4*)(bs);
                pb[2*s2 + 1] = *(const float4*)(bs + NH);
            }
        }

        const unsigned* As = sA + s * BM * AR;
        const unsigned* Bs = sB + s * 16 * BR2;

#pragma unroll
        for (int kk = 0; kk < 2; kk++) {
            int k8 = kk * 8;
            unsigned a[4][4];
#pragma unroll
            for (int mi = 0; mi < 4; mi++) {
                int mb = wm + mi * 16 + grp;
                a[mi][0] = As[(mb    ) * AR + k8 + tig    ];
                a[mi][1] = As[(mb + 8) * AR + k8 + tig    ];
                a[mi][2] = As[(mb    ) * AR + k8 + tig + 4];
                a[mi][3] = As[(mb + 8) * AR + k8 + tig + 4];
            }
#pragma unroll
            for (int nj = 0; nj < 8; nj++) {
                int nb = wn + nj * 8 + grp;
                unsigned b[2];
                b[0] = Bs[(k8 + tig    ) * BR2 + nb];
                b[1] = Bs[(k8 + tig + 4) * BR2 + nb];
#pragma unroll
                for (int mi = 0; mi < 4; mi++) mma16(acc[mi][nj], a[mi], b);
            }
        }

        if (nxt) {
            int sn = s ^ 1;
            unsigned* An = sA + sn * BM * AR + tid * AR;
            unsigned* Bn = sB + sn * 16 * BR2;
            *(uint4*)(An) = pa[0]; *(uint4*)(An + 4) = pa[1];
            *(uint4*)(An + 8) = pa[2]; *(uint4*)(An + 12) = pa[3];
#pragma unroll
            for (int s2 = 0; s2 < 4; s2++)
                *(uint4*)(Bn + bOffs[s2]) = hpack_rows(pb[2*s2], pb[2*s2 + 1]);
        }
        __syncthreads();
    }

#pragma unroll
    for (int mi = 0; mi < 4; mi++) {
#pragma unroll
        for (int nj = 0; nj < 8; nj++) {
            int mloc = wm + mi * 16 + grp;
            int ncol = n0 + wn + nj * 8 + tig * 2;
#pragma unroll
            for (int h = 0; h < 2; h++) {
                int ml = mloc + h * 8;
                int mr = m0 + ml;
                if (mr < cnt) {
                    int   t = toks[ml];
                    float w = wts[ml];
                    float* dst = out + (size_t)t * NH + ncol;
                    asm volatile("red.global.add.v2.f32 [%0], {%1,%2};"
                                 :: "l"(dst), "f"(w * acc[mi][nj][2*h]),
                                    "f"(w * acc[mi][nj][2*h + 1]) : "memory");
                }
            }
        }
    }
}

// ---------------- launch ----------------
extern "C" void kernel_launch(void* const* d_in, const int* in_sizes, int n_in,
                              void* d_out, int out_size)
{
    const float* hidden = (const float*)d_in[0];
    const int*   idx    = (const int*)  d_in[1];
    const float* topw   = (const float*)d_in[2];
    const float* gate_w = (const float*)d_in[3];
    const float* up_w   = (const float*)d_in[4];
    const float* down_w = (const float*)d_in[5];
    float* out = (float*)d_out;

    int smem1 = (A_WORDS + 2 * B1_WORDS) * 4 + BM * 4;
    int smem2 = (A_WORDS + B2_WORDS) * 4 + BM * 8;
    static int configured = 0;
    if (!configured) {
        cudaFuncSetAttribute(k_gemm1, cudaFuncAttributeMaxDynamicSharedMemorySize, smem1);
        cudaFuncSetAttribute(k_gemm2, cudaFuncAttributeMaxDynamicSharedMemorySize, smem2);
        configured = 1;
    }

    k_route<<<1, 1024>>>(idx, topw);
    k_prep<<<(NT * NH / 8) / 256, 256>>>(hidden, out);

    // grid.x = experts (fast), grid.y = N-tiles, grid.z = M-tiles
    dim3 g1(NE, NI / 64, NP / BM);
    k_gemm1<<<g1, 128, smem1>>>(gate_w, up_w);

    dim3 g2(NE, NH / 128, NP / BM);
    k_gemm2<<<g2, 128, smem2>>>(down_w, out);
}

// round 15
// speedup vs baseline: 2.1333x; 1.0284x over previous
#include <cuda_runtime.h>
#include <cuda_fp16.h>
#include <math.h>

#define NT 2048
#define NH 2048
#define NI 1408
#define NE 8
#define TK 2
#define NP (NT*TK)

#define BM 128
#define BK 32
#define AR 20     // A [m][k/2] words + pad
#define BR1 72    // gemm1 B [k/2][64n] + 8 pad (72%32=8 -> conflict-free)
#define BR2 72    // gemm2 B [k/2][64n] x2 matrices

#define A_WORDS  (2 * BM * AR)      // double buffered
#define B1_WORDS (2 * 16 * BR1)
#define B2_WORDS (2 * 16 * BR2)

// ---------------- scratch ----------------
__device__ int      g_cnt[NE];
__device__ int      g_off[NE + 1];
__device__ int      g_tok[NP];
__device__ float    g_wt[NP];
__device__ unsigned g_hidh[(size_t)NT * NH / 2];   // fp16x2 hidden (8 MB)
__device__ unsigned g_acth[(size_t)NP * NI / 2];   // fp16x2 activations (11.5 MB)

// ---------------- fused routing ----------------
__global__ __launch_bounds__(1024) void k_route(
    const int* __restrict__ idx, const float* __restrict__ w)
{
    __shared__ int scnt[NE], soff[NE], sfill[NE];
    int tid = threadIdx.x;
    if (tid < NE) { scnt[tid] = 0; sfill[tid] = 0; }
    __syncthreads();
    int my_e[4];
#pragma unroll
    for (int j = 0; j < 4; j++) {
        int i = tid + j * 1024;
        my_e[j] = idx[i];
        atomicAdd(&scnt[my_e[j]], 1);
    }
    __syncthreads();
    if (tid == 0) {
        int s = 0;
        for (int e = 0; e < NE; e++) {
            soff[e] = s; g_off[e] = s; g_cnt[e] = scnt[e]; s += scnt[e];
        }
        g_off[NE] = s;
    }
    __syncthreads();
#pragma unroll
    for (int j = 0; j < 4; j++) {
        int i = tid + j * 1024;
        int e = my_e[j];
        int pos = soff[e] + atomicAdd(&sfill[e], 1);
        g_tok[pos] = i / TK;
        g_wt[pos]  = w[i];
    }
}

// ---------------- fp16 helpers ----------------
__device__ __forceinline__ unsigned hpack(float lo, float hi) {
    __half2 h = __floats2half2_rn(lo, hi);
    return *(unsigned*)&h;
}
__device__ __forceinline__ uint4 hpack_rows(float4 r0, float4 r1) {
    uint4 w;
    w.x = hpack(r0.x, r1.x); w.y = hpack(r0.y, r1.y);
    w.z = hpack(r0.z, r1.z); w.w = hpack(r0.w, r1.w);
    return w;
}
__device__ __forceinline__ uint4 hpack_k(float4 a, float4 b) {
    uint4 w;
    w.x = hpack(a.x, a.y); w.y = hpack(a.z, a.w);
    w.z = hpack(b.x, b.y); w.w = hpack(b.z, b.w);
    return w;
}
__device__ __forceinline__ void mma16(float* c, const unsigned* a, const unsigned* b) {
    asm volatile(
        "mma.sync.aligned.m16n8k16.row.col.f32.f16.f16.f32 "
        "{%0,%1,%2,%3},{%4,%5,%6,%7},{%8,%9},{%0,%1,%2,%3};"
        : "+f"(c[0]), "+f"(c[1]), "+f"(c[2]), "+f"(c[3])
        : "r"(a[0]), "r"(a[1]), "r"(a[2]), "r"(a[3]), "r"(b[0]), "r"(b[1]));
}

// pre-round hidden to fp16 + zero output
__global__ void k_prep(const float* __restrict__ hidden, float* __restrict__ out) {
    int i = blockIdx.x * blockDim.x + threadIdx.x;
    float4 a = ((const float4*)hidden)[2 * i];
    float4 b = ((const float4*)hidden)[2 * i + 1];
    ((uint4*)g_hidh)[i] = hpack_k(a, b);
    ((float4*)out)[2 * i]     = make_float4(0.f, 0.f, 0.f, 0.f);
    ((float4*)out)[2 * i + 1] = make_float4(0.f, 0.f, 0.f, 0.f);
}

// ---------------- GEMM1: act = silu(X Wg) * (X Wu) ----------------
// CTA 128M x 64N x 2mat, 4 warps (2M x 2N), warp tile 64M x 32N x 2mat.  (R14 config)
__global__ __launch_bounds__(128, 2) void k_gemm1(
    const float* __restrict__ gate_w,
    const float* __restrict__ up_w)
{
    extern __shared__ unsigned sm[];
    unsigned* sA  = sm;
    unsigned* sBg = sA + A_WORDS;
    unsigned* sBu = sBg + B1_WORDS;
    int* toks = (int*)(sBu + B1_WORDS);

    int e = blockIdx.x % NE, cnt = g_cnt[e];
    int m0 = blockIdx.z * BM;
    if (m0 >= cnt) return;
    int base = g_off[e];
    int n0 = blockIdx.y * 64;
    int tid = threadIdx.x;

    if (tid < BM) {
        int m = m0 + tid;
        toks[tid] = (m < cnt) ? g_tok[base + m] : g_tok[base];
    }
    __syncthreads();

    const float* gp = gate_w + (size_t)e * NH * NI;
    const float* up = up_w   + (size_t)e * NH * NI;

    const unsigned* aSrc = g_hidh + (size_t)toks[tid] * (NH / 2);
    unsigned* aDst0 = sA + tid * AR;
    int k2a = tid >> 4,         n4a = (tid & 15) << 2;
    int k2b = (tid + 128) >> 4, n4b = ((tid + 128) & 15) << 2;
    const float* gA = gp + (size_t)(2 * k2a) * NI + n0 + n4a;
    const float* gB = gp + (size_t)(2 * k2b) * NI + n0 + n4b;
    const float* uA = up + (size_t)(2 * k2a) * NI + n0 + n4a;
    const float* uB = up + (size_t)(2 * k2b) * NI + n0 + n4b;
    unsigned bOffA = k2a * BR1 + n4a, bOffB = k2b * BR1 + n4b;

    {
        uint4 c0 = ((const uint4*)aSrc)[0], c1 = ((const uint4*)aSrc)[1];
        uint4 c2 = ((const uint4*)aSrc)[2], c3 = ((const uint4*)aSrc)[3];
        *(uint4*)(aDst0) = c0; *(uint4*)(aDst0 + 4) = c1;
        *(uint4*)(aDst0 + 8) = c2; *(uint4*)(aDst0 + 12) = c3;
        *(uint4*)(sBg + bOffA) = hpack_rows(*(const float4*)gA, *(const float4*)(gA + NI));
        *(uint4*)(sBg + bOffB) = hpack_rows(*(const float4*)gB, *(const float4*)(gB + NI));
        *(uint4*)(sBu + bOffA) = hpack_rows(*(const float4*)uA, *(const float4*)(uA + NI));
        *(uint4*)(sBu + bOffB) = hpack_rows(*(const float4*)uB, *(const float4*)(uB + NI));
    }
    __syncthreads();

    int lane = tid & 31, wid = tid >> 5;
    int wm = (wid & 1) * 64, wn = (wid >> 1) * 32;
    int grp = lane >> 2, tig = lane & 3;

    float accg[4][4][4] = {}, accu[4][4][4] = {};
    uint4 pa[4];
    float4 pg[4], pu[4];

    for (int k0 = 0; k0 < NH; k0 += BK) {
        int s = (k0 / BK) & 1;
        bool nxt = (k0 + BK) < NH;
        if (nxt) {
            int kn = k0 + BK;
            const unsigned* as = aSrc + (kn >> 1);
            pa[0] = ((const uint4*)as)[0]; pa[1] = ((const uint4*)as)[1];
            pa[2] = ((const uint4*)as)[2]; pa[3] = ((const uint4*)as)[3];
            pg[0] = *(const float4*)(gA + (size_t)kn * NI);
            pg[1] = *(const float4*)(gA + (size_t)(kn + 1) * NI);
            pg[2] = *(const float4*)(gB + (size_t)kn * NI);
            pg[3] = *(const float4*)(gB + (size_t)(kn + 1) * NI);
            pu[0] = *(const float4*)(uA + (size_t)kn * NI);
            pu[1] = *(const float4*)(uA + (size_t)(kn + 1) * NI);
            pu[2] = *(const float4*)(uB + (size_t)kn * NI);
            pu[3] = *(const float4*)(uB + (size_t)(kn + 1) * NI);
        }

        const unsigned* As = sA  + s * BM * AR;
        const unsigned* Bg = sBg + s * 16 * BR1;
        const unsigned* Bu = sBu + s * 16 * BR1;

#pragma unroll
        for (int kk = 0; kk < 2; kk++) {
            int k8 = kk * 8;
            unsigned a[4][4];
#pragma unroll
            for (int mi = 0; mi < 4; mi++) {
                int mb = wm + mi * 16 + grp;
                a[mi][0] = As[(mb    ) * AR + k8 + tig    ];
                a[mi][1] = As[(mb + 8) * AR + k8 + tig    ];
                a[mi][2] = As[(mb    ) * AR + k8 + tig + 4];
                a[mi][3] = As[(mb + 8) * AR + k8 + tig + 4];
            }
#pragma unroll
            for (int nj = 0; nj < 4; nj++) {
                int nb = wn + nj * 8 + grp;
                unsigned b[2];
                b[0] = Bg[(k8 + tig    ) * BR1 + nb];
                b[1] = Bg[(k8 + tig + 4) * BR1 + nb];
#pragma unroll
                for (int mi = 0; mi < 4; mi++) mma16(accg[mi][nj], a[mi], b);
                b[0] = Bu[(k8 + tig    ) * BR1 + nb];
                b[1] = Bu[(k8 + tig + 4) * BR1 + nb];
#pragma unroll
                for (int mi = 0; mi < 4; mi++) mma16(accu[mi][nj], a[mi], b);
            }
        }

        if (nxt) {
            int sn = s ^ 1;
            unsigned* An  = sA  + sn * BM * AR + tid * AR;
            unsigned* Bgn = sBg + sn * 16 * BR1;
            unsigned* Bun = sBu + sn * 16 * BR1;
            *(uint4*)(An) = pa[0]; *(uint4*)(An + 4) = pa[1];
            *(uint4*)(An + 8) = pa[2]; *(uint4*)(An + 12) = pa[3];
            *(uint4*)(Bgn + bOffA) = hpack_rows(pg[0], pg[1]);
            *(uint4*)(Bgn + bOffB) = hpack_rows(pg[2], pg[3]);
            *(uint4*)(Bun + bOffA) = hpack_rows(pu[0], pu[1]);
            *(uint4*)(Bun + bOffB) = hpack_rows(pu[2], pu[3]);
        }
        __syncthreads();
    }

#pragma unroll
    for (int mi = 0; mi < 4; mi++) {
#pragma unroll
        for (int nj = 0; nj < 4; nj++) {
            int mrow = wm + mi * 16 + grp;
            int ncol = n0 + wn + nj * 8 + tig * 2;
#pragma unroll
            for (int h = 0; h < 2; h++) {
                int mr = m0 + mrow + h * 8;
                if (mr < cnt) {
                    float g0 = accg[mi][nj][2*h],     u0 = accu[mi][nj][2*h];
                    float g1 = accg[mi][nj][2*h + 1], u1 = accu[mi][nj][2*h + 1];
                    float v0 = (g0 / (1.f + __expf(-g0))) * u0;
                    float v1 = (g1 / (1.f + __expf(-g1))) * u1;
                    g_acth[(size_t)(base + mr) * (NI / 2) + (ncol >> 1)] = hpack(v0, v1);
                }
            }
        }
    }
}

// ---------------- GEMM2: out[token] += wt * (act . Wd), dual-N ----------------
// R13 config: 256 threads, 8 warps (4M x 2N), warp 32M x 32N x dual-N matrices.
__global__ __launch_bounds__(256, 2) void k_gemm2(
    const float* __restrict__ down_w,
    float* __restrict__ out)
{
    extern __shared__ unsigned sm[];
    unsigned* sA  = sm;
    unsigned* sB0 = sA + A_WORDS;
    unsigned* sB1 = sB0 + B2_WORDS;
    int*   toks = (int*)(sB1 + B2_WORDS);
    float* wts  = (float*)(toks + BM);

    int e = blockIdx.z, cnt = g_cnt[e];
    int m0 = blockIdx.x * BM;
    if (m0 >= cnt) return;
    int base = g_off[e];
    int n0 = blockIdx.y * 128;
    int tid = threadIdx.x;

    if (tid < BM) {
        int m = m0 + tid;
        toks[tid] = (m < cnt) ? g_tok[base + m] : 0;
        wts[tid]  = (m < cnt) ? g_wt[base + m] : 0.f;
    }
    __syncthreads();

    const float* dp = down_w + (size_t)e * NI * NH;

    int a_m = tid >> 1, a_w = (tid & 1) << 3;
    int am = m0 + a_m;
    const unsigned* aSrc = g_acth + (size_t)(base + (am < cnt ? am : m0)) * (NI / 2) + a_w;
    unsigned* aDstBase = sA + a_m * AR + a_w;
    int b_k2 = tid >> 4, b_n4 = (tid & 15) << 2;
    const float* bSrc0 = dp + (size_t)(2 * b_k2) * NH + n0 + b_n4;
    const float* bSrc1 = bSrc0 + 64;
    unsigned bOff = b_k2 * BR2 + b_n4;

    {
        *(uint4*)(aDstBase)     = *(const uint4*)(aSrc);
        *(uint4*)(aDstBase + 4) = *(const uint4*)(aSrc + 4);
        float4 v00 = *(const float4*)(bSrc0);
        float4 v01 = *(const float4*)(bSrc0 + NH);
        float4 v10 = *(const float4*)(bSrc1);
        float4 v11 = *(const float4*)(bSrc1 + NH);
        *(uint4*)(sB0 + bOff) = hpack_rows(v00, v01);
        *(uint4*)(sB1 + bOff) = hpack_rows(v10, v11);
    }
    __syncthreads();

    int lane = tid & 31, wid = tid >> 5;
    int wm = (wid & 3) * 32, wn = (wid >> 2) * 32;
    int grp = lane >> 2, tig = lane & 3;

    float acc0[2][4][4] = {}, acc1[2][4][4] = {};
    uint4 pa[2];
    float4 pb0[2], pb1[2];

    for (int k0 = 0; k0 < NI; k0 += BK) {
        int s = (k0 / BK) & 1;
        bool nxt = (k0 + BK) < NI;
        if (nxt) {
            int kn = k0 + BK;
            pa[0] = *(const uint4*)(aSrc + (kn >> 1));
            pa[1] = *(const uint4*)(aSrc + (kn >> 1) + 4);
            pb0[0] = *(const float4*)(bSrc0 + (size_t)kn * NH);
            pb0[1] = *(const float4*)(bSrc0 + (size_t)(kn + 1) * NH);
            pb1[0] = *(const float4*)(bSrc1 + (size_t)kn * NH);
            pb1[1] = *(const float4*)(bSrc1 + (size_t)(kn + 1) * NH);
        }

        const unsigned* As = sA  + s * BM * AR;
        const unsigned* B0 = sB0 + s * 16 * BR2;
        const unsigned* B1 = sB1 + s * 16 * BR2;

#pragma unroll
        for (int kk = 0; kk < 2; kk++) {
            int k8 = kk * 8;
            unsigned a[2][4];
#pragma unroll
            for (int mi = 0; mi < 2; mi++) {
                int mb = wm + mi * 16 + grp;
                a[mi][0] = As[(mb    ) * AR + k8 + tig    ];
                a[mi][1] = As[(mb + 8) * AR + k8 + tig    ];
                a[mi][2] = As[(mb    ) * AR + k8 + tig + 4];
                a[mi][3] = As[(mb + 8) * AR + k8 + tig + 4];
            }
#pragma unroll
            for (int nj = 0; nj < 4; nj++) {
                int nb = wn + nj * 8 + grp;
                unsigned b[2];
                b[0] = B0[(k8 + tig    ) * BR2 + nb];
                b[1] = B0[(k8 + tig + 4) * BR2 + nb];
                mma16(acc0[0][nj], a[0], b);
                mma16(acc0[1][nj], a[1], b);
                b[0] = B1[(k8 + tig    ) * BR2 + nb];
                b[1] = B1[(k8 + tig + 4) * BR2 + nb];
                mma16(acc1[0][nj], a[0], b);
                mma16(acc1[1][nj], a[1], b);
            }
        }

        if (nxt) {
            int sn = s ^ 1;
            unsigned* An  = sA  + sn * BM * AR + a_m * AR + a_w;
            unsigned* Bn0 = sB0 + sn * 16 * BR2;
            unsigned* Bn1 = sB1 + sn * 16 * BR2;
            *(uint4*)(An)     = pa[0];
            *(uint4*)(An + 4) = pa[1];
            *(uint4*)(Bn0 + bOff) = hpack_rows(pb0[0], pb0[1]);
            *(uint4*)(Bn1 + bOff) = hpack_rows(pb1[0], pb1[1]);
        }
        __syncthreads();
    }

#pragma unroll
    for (int mi = 0; mi < 2; mi++) {
#pragma unroll
        for (int nj = 0; nj < 4; nj++) {
            int mloc = wm + mi * 16 + grp;
            int ncol = n0 + wn + nj * 8 + tig * 2;
#pragma unroll
            for (int h = 0; h < 2; h++) {
                int ml = mloc + h * 8;
                int mr = m0 + ml;
                if (mr < cnt) {
                    int   t = toks[ml];
                    float w = wts[ml];
                    float* dst = out + (size_t)t * NH + ncol;
                    asm volatile("red.global.add.v2.f32 [%0], {%1,%2};"
                                 :: "l"(dst), "f"(w * acc0[mi][nj][2*h]),
                                    "f"(w * acc0[mi][nj][2*h + 1]) : "memory");
                    asm volatile("red.global.add.v2.f32 [%0], {%1,%2};"
                                 :: "l"(dst + 64), "f"(w * acc1[mi][nj][2*h]),
                                    "f"(w * acc1[mi][nj][2*h + 1]) : "memory");
                }
            }
        }
    }
}

// ---------------- launch ----------------
extern "C" void kernel_launch(void* const* d_in, const int* in_sizes, int n_in,
                              void* d_out, int out_size)
{
    const float* hidden = (const float*)d_in[0];
    const int*   idx    = (const int*)  d_in[1];
    const float* topw   = (const float*)d_in[2];
    const float* gate_w = (const float*)d_in[3];
    const float* up_w   = (const float*)d_in[4];
    const float* down_w = (const float*)d_in[5];
    float* out = (float*)d_out;

    int smem1 = (A_WORDS + 2 * B1_WORDS) * 4 + BM * 4;
    int smem2 = (A_WORDS + 2 * B2_WORDS) * 4 + BM * 8;
    static int configured = 0;
    if (!configured) {
        cudaFuncSetAttribute(k_gemm1, cudaFuncAttributeMaxDynamicSharedMemorySize, smem1);
        cudaFuncSetAttribute(k_gemm2, cudaFuncAttributeMaxDynamicSharedMemorySize, smem2);
        configured = 1;
    }

    k_route<<<1, 1024>>>(idx, topw);
    k_prep<<<(NT * NH / 8) / 256, 256>>>(hidden, out);

    dim3 g1(NE, NI / 64, NP / BM);
    k_gemm1<<<g1, 128, smem1>>>(gate_w, up_w);

    dim3 g2(NP / BM, NH / 128, NE);
    k_gemm2<<<g2, 256, smem2>>>(down_w, out);
}